// round 1
// baseline (speedup 1.0000x reference)
#include <cuda_runtime.h>
#include <cuda_bf16.h>
#include <math.h>

// Problem constants (fixed shapes)
#define B_    2
#define NH_   4
#define T_    8
#define H_    14
#define W_    14
#define N_    1568          // T*H*W
#define DIM_  384
#define HD_   96
#define BH_   (B_*NH_)      // 8
#define M_    (B_*N_)       // 3136
#define EPS_  1e-6f

// ---------------- scratch (device globals; no runtime allocation) ----------
__device__ float g_q_raw[BH_ * N_ * HD_];
__device__ float g_k_raw[BH_ * N_ * HD_];
__device__ float g_v_raw[BH_ * N_ * HD_];
__device__ float g_q[BH_ * N_ * HD_];
__device__ float g_k[BH_ * N_ * HD_];
__device__ float g_v[BH_ * N_ * HD_];
__device__ float g_attn[(size_t)BH_ * N_ * N_];     // 19.7M floats
__device__ float g_relh[BH_ * N_ * H_];
__device__ float g_relw[BH_ * N_ * W_];
__device__ float g_relt[BH_ * N_ * T_];
__device__ float g_ctx[B_ * N_ * DIM_];

// ---------------- shared NT GEMM tile: C[m,n] = sum_k A[m,k]*Bw[n,k] -------
// BM=BN=64, BK=16, block(16,16), per-thread 4x4
__device__ __forceinline__ void gemm_nt_tile(const float* __restrict__ A,
                                             const float* __restrict__ Bw,
                                             int M, int Nc, int K,
                                             int m0, int n0, float acc[4][4]) {
    __shared__ float As[16][65];
    __shared__ float Bs[16][65];
    const int tid = threadIdx.y * 16 + threadIdx.x;
    for (int k0 = 0; k0 < K; k0 += 16) {
        #pragma unroll
        for (int i = 0; i < 4; i++) {
            int lin = tid + 256 * i;          // 0..1023
            int r = lin >> 4, kk = lin & 15;
            int gr = m0 + r;
            As[kk][r] = (gr < M) ? A[(size_t)gr * K + k0 + kk] : 0.f;
            int gc = n0 + r;
            Bs[kk][r] = (gc < Nc) ? Bw[(size_t)gc * K + k0 + kk] : 0.f;
        }
        __syncthreads();
        #pragma unroll
        for (int kk = 0; kk < 16; kk++) {
            float af[4], bf[4];
            #pragma unroll
            for (int t = 0; t < 4; t++) af[t] = As[kk][threadIdx.y * 4 + t];
            #pragma unroll
            for (int t = 0; t < 4; t++) bf[t] = Bs[kk][threadIdx.x * 4 + t];
            #pragma unroll
            for (int a = 0; a < 4; a++)
                #pragma unroll
                for (int b = 0; b < 4; b++) acc[a][b] += af[a] * bf[b];
        }
        __syncthreads();
    }
}

// ---------------- K1: fused QKV projection, scatter to per-head buffers ----
__global__ void k_qkv(const float* __restrict__ x, const float* __restrict__ qkv_w) {
    int n0 = blockIdx.x * 64, m0 = blockIdx.y * 64;
    float acc[4][4] = {};
    gemm_nt_tile(x, qkv_w, M_, 3 * DIM_, DIM_, m0, n0, acc);
    #pragma unroll
    for (int a = 0; a < 4; a++) {
        int m = m0 + threadIdx.y * 4 + a;
        int b = m / N_, n = m % N_;
        #pragma unroll
        for (int bb = 0; bb < 4; bb++) {
            int o = n0 + threadIdx.x * 4 + bb;
            int s = o / DIM_;
            int rem = o - s * DIM_;
            int head = rem / HD_;
            int c = rem - head * HD_;
            float* dst = (s == 0) ? g_q_raw : (s == 1) ? g_k_raw : g_v_raw;
            dst[((size_t)(b * NH_ + head) * N_ + n) * HD_ + c] = acc[a][bb];
        }
    }
}

// ---------------- K2: depthwise 3x3x3 conv + LayerNorm (q,k,v) ------------
__global__ void k_conv_ln(const float* __restrict__ wq, const float* __restrict__ wk,
                          const float* __restrict__ wv,
                          const float* __restrict__ gq, const float* __restrict__ bq,
                          const float* __restrict__ gk, const float* __restrict__ bk,
                          const float* __restrict__ gv, const float* __restrict__ bv) {
    int n = blockIdx.x, bh = blockIdx.y, z = blockIdx.z;
    const float* inb  = (z == 0) ? g_q_raw : (z == 1) ? g_k_raw : g_v_raw;
    float*       outb = (z == 0) ? g_q     : (z == 1) ? g_k     : g_v;
    const float* wt    = (z == 0) ? wq : (z == 1) ? wk : wv;
    const float* gamma = (z == 0) ? gq : (z == 1) ? gk : gv;
    const float* beta  = (z == 0) ? bq : (z == 1) ? bk : bv;
    int c = threadIdx.x;                 // 0..127 (96 active)
    int tt = n / (H_ * W_);
    int rem = n - tt * (H_ * W_);
    int hh = rem / W_, ww = rem - (rem / W_) * W_;

    float val = 0.f;
    if (c < HD_) {
        const float* wc = wt + c * 27;
        #pragma unroll
        for (int dt = -1; dt <= 1; dt++) {
            int t2 = tt + dt;
            if (t2 < 0 || t2 >= T_) continue;
            #pragma unroll
            for (int dh = -1; dh <= 1; dh++) {
                int h2 = hh + dh;
                if (h2 < 0 || h2 >= H_) continue;
                #pragma unroll
                for (int dw = -1; dw <= 1; dw++) {
                    int w2 = ww + dw;
                    if (w2 < 0 || w2 >= W_) continue;
                    int n2 = (t2 * H_ + h2) * W_ + w2;
                    val += wc[(dt + 1) * 9 + (dh + 1) * 3 + (dw + 1)] *
                           inb[((size_t)bh * N_ + n2) * HD_ + c];
                }
            }
        }
    }
    __shared__ float ssum[128], ssq[128];
    ssum[c] = (c < HD_) ? val : 0.f;
    ssq[c]  = (c < HD_) ? val * val : 0.f;
    __syncthreads();
    for (int s = 64; s > 0; s >>= 1) {
        if (c < s) { ssum[c] += ssum[c + s]; ssq[c] += ssq[c + s]; }
        __syncthreads();
    }
    float mean = ssum[0] * (1.f / HD_);
    float var  = ssq[0] * (1.f / HD_) - mean * mean;
    float rstd = rsqrtf(var + EPS_);
    if (c < HD_)
        outb[((size_t)bh * N_ + n) * HD_ + c] = (val - mean) * rstd * gamma[c] + beta[c];
}

// ---------------- K3: decomposed rel-pos bias projections -----------------
__global__ void k_rel(const float* __restrict__ rph, const float* __restrict__ rpw,
                      const float* __restrict__ rpt) {
    int idx = blockIdx.x * 256 + threadIdx.x;
    const int total = BH_ * N_ * 36;     // 14 + 14 + 8 outputs per (bh,i)
    if (idx >= total) return;
    int r = idx % 36;
    int bhi = idx / 36;                  // bh*N_ + i
    int i = bhi % N_;
    int it = i / (H_ * W_);
    int rem = i - it * (H_ * W_);
    int ih = rem / W_, iw = rem - (rem / W_) * W_;

    const float* qrow = g_q + (size_t)bhi * HD_;
    const float* tab;
    float* dst;
    if (r < 14)      { int k = r;      tab = rph + (ih - k + (H_ - 1)) * HD_; dst = g_relh + (size_t)bhi * H_ + k; }
    else if (r < 28) { int k = r - 14; tab = rpw + (iw - k + (W_ - 1)) * HD_; dst = g_relw + (size_t)bhi * W_ + k; }
    else             { int k = r - 28; tab = rpt + (it - k + (T_ - 1)) * HD_; dst = g_relt + (size_t)bhi * T_ + k; }
    float s = 0.f;
    #pragma unroll 8
    for (int c = 0; c < HD_; c++) s += qrow[c] * tab[c];
    *dst = s;
}

// ---------------- K4: attn = scale*q@k^T + rel biases ----------------------
__global__ void k_qk() {
    int bh = blockIdx.z;
    const float* A  = g_q + (size_t)bh * N_ * HD_;
    const float* Bm = g_k + (size_t)bh * N_ * HD_;
    int m0 = blockIdx.y * 64, n0 = blockIdx.x * 64;
    float acc[4][4] = {};
    gemm_nt_tile(A, Bm, N_, N_, HD_, m0, n0, acc);
    const float scale = 0.102062072615965754f;  // 96^-0.5
    #pragma unroll
    for (int a = 0; a < 4; a++) {
        int i = m0 + threadIdx.y * 4 + a;
        if (i >= N_) continue;
        size_t ri = (size_t)bh * N_ + i;
        #pragma unroll
        for (int bb = 0; bb < 4; bb++) {
            int j = n0 + threadIdx.x * 4 + bb;
            if (j >= N_) continue;
            int jt = j / (H_ * W_);
            int jr = j - jt * (H_ * W_);
            int jh = jr / W_, jw = jr - (jr / W_) * W_;
            g_attn[ri * N_ + j] = acc[a][bb] * scale
                                + g_relt[ri * T_ + jt]
                                + g_relh[ri * H_ + jh]
                                + g_relw[ri * W_ + jw];
        }
    }
}

// ---------------- K5: row softmax over 1568 --------------------------------
__global__ void k_softmax() {
    size_t row = blockIdx.x;
    float* p = g_attn + row * N_;
    int tid = threadIdx.x;
    float v[7];
    int cnt = 0;
    float mx = -1e30f;
    for (int j = tid; j < N_; j += 256) {
        float x = p[j];
        v[cnt++] = x;
        mx = fmaxf(mx, x);
    }
    __shared__ float sm[256];
    sm[tid] = mx;
    __syncthreads();
    for (int s = 128; s > 0; s >>= 1) {
        if (tid < s) sm[tid] = fmaxf(sm[tid], sm[tid + s]);
        __syncthreads();
    }
    mx = sm[0];
    __syncthreads();
    float sum = 0.f;
    for (int t = 0; t < cnt; t++) { v[t] = expf(v[t] - mx); sum += v[t]; }
    sm[tid] = sum;
    __syncthreads();
    for (int s = 128; s > 0; s >>= 1) {
        if (tid < s) sm[tid] += sm[tid + s];
        __syncthreads();
    }
    float inv = 1.f / sm[0];
    cnt = 0;
    for (int j = tid; j < N_; j += 256) p[j] = v[cnt++] * inv;
}

// ---------------- K6: out = attn @ v + q (NN GEMM, fused residual) ---------
// BM=32, BN=96(full), BK=16, block(16,16), per-thread 2x6
__global__ void k_av() {
    int bh = blockIdx.z;
    int i0 = blockIdx.x * 32;
    const float* A = g_attn + (size_t)bh * N_ * N_;
    const float* V = g_v + (size_t)bh * N_ * HD_;
    __shared__ float As[32][17];
    __shared__ float Bs[16][97];
    const int tid = threadIdx.y * 16 + threadIdx.x;
    float acc[2][6] = {};
    for (int j0 = 0; j0 < N_; j0 += 16) {
        #pragma unroll
        for (int i = 0; i < 2; i++) {
            int lin = tid + 256 * i;        // 0..511
            int r = lin >> 4, kk = lin & 15;
            As[r][kk] = A[(size_t)(i0 + r) * N_ + j0 + kk];
        }
        #pragma unroll
        for (int i = 0; i < 6; i++) {
            int lin = tid + 256 * i;        // 0..1535
            int r = lin / 96, c = lin - r * 96;
            Bs[r][c] = V[(size_t)(j0 + r) * HD_ + c];
        }
        __syncthreads();
        #pragma unroll
        for (int kk = 0; kk < 16; kk++) {
            float af[2], bf[6];
            af[0] = As[threadIdx.y * 2 + 0][kk];
            af[1] = As[threadIdx.y * 2 + 1][kk];
            #pragma unroll
            for (int t = 0; t < 6; t++) bf[t] = Bs[kk][threadIdx.x + 16 * t];
            #pragma unroll
            for (int a = 0; a < 2; a++)
                #pragma unroll
                for (int t = 0; t < 6; t++) acc[a][t] += af[a] * bf[t];
        }
        __syncthreads();
    }
    int b = bh / NH_, nh = bh % NH_;
    #pragma unroll
    for (int a = 0; a < 2; a++) {
        int i = i0 + threadIdx.y * 2 + a;
        #pragma unroll
        for (int t = 0; t < 6; t++) {
            int c = threadIdx.x + 16 * t;
            float qv = g_q[((size_t)bh * N_ + i) * HD_ + c];
            g_ctx[(((size_t)b * N_ + i) * NH_ + nh) * HD_ + c] = acc[a][t] + qv;
        }
    }
}

// ---------------- K7: output projection + bias -----------------------------
__global__ void k_proj(const float* __restrict__ proj_w, const float* __restrict__ proj_b,
                       float* __restrict__ out) {
    int n0 = blockIdx.x * 64, m0 = blockIdx.y * 64;
    float acc[4][4] = {};
    gemm_nt_tile(g_ctx, proj_w, M_, DIM_, DIM_, m0, n0, acc);
    #pragma unroll
    for (int a = 0; a < 4; a++) {
        int m = m0 + threadIdx.y * 4 + a;
        #pragma unroll
        for (int bb = 0; bb < 4; bb++) {
            int o = n0 + threadIdx.x * 4 + bb;
            out[(size_t)m * DIM_ + o] = acc[a][bb] + proj_b[o];
        }
    }
}

// ---------------- launch ----------------------------------------------------
extern "C" void kernel_launch(void* const* d_in, const int* in_sizes, int n_in,
                              void* d_out, int out_size) {
    const float* x      = (const float*)d_in[0];
    const float* qkv_w  = (const float*)d_in[1];
    const float* proj_w = (const float*)d_in[2];
    const float* proj_b = (const float*)d_in[3];
    const float* pqw    = (const float*)d_in[4];
    const float* pkw    = (const float*)d_in[5];
    const float* pvw    = (const float*)d_in[6];
    const float* nqw    = (const float*)d_in[7];
    const float* nqb    = (const float*)d_in[8];
    const float* nkw    = (const float*)d_in[9];
    const float* nkb    = (const float*)d_in[10];
    const float* nvw    = (const float*)d_in[11];
    const float* nvb    = (const float*)d_in[12];
    const float* rph    = (const float*)d_in[13];
    const float* rpw    = (const float*)d_in[14];
    const float* rpt    = (const float*)d_in[15];
    float* out = (float*)d_out;

    dim3 t16(16, 16);
    k_qkv<<<dim3(18, 49), t16>>>(x, qkv_w);
    k_conv_ln<<<dim3(N_, BH_, 3), 128>>>(pqw, pkw, pvw, nqw, nqb, nkw, nkb, nvw, nvb);
    k_rel<<<(BH_ * N_ * 36 + 255) / 256, 256>>>(rph, rpw, rpt);
    k_qk<<<dim3(25, 25, BH_), t16>>>();
    k_softmax<<<BH_ * N_, 256>>>();
    k_av<<<dim3(49, 1, BH_), t16>>>();
    k_proj<<<dim3(6, 49), t16>>>(proj_w, proj_b, out);
}

// round 2
// speedup vs baseline: 1.1269x; 1.1269x over previous
#include <cuda_runtime.h>
#include <cuda_bf16.h>
#include <math.h>

// Problem constants (fixed shapes)
#define B_    2
#define NH_   4
#define T_    8
#define H_    14
#define W_    14
#define N_    1568          // T*H*W
#define DIM_  384
#define HD_   96
#define BH_   (B_*NH_)      // 8
#define M_    (B_*N_)       // 3136
#define EPS_  1e-6f
#define SCALE_ 0.1020620726159657f   // 96^-0.5

// ---------------- scratch (device globals; no runtime allocation) ----------
__device__ float g_q_raw[BH_ * N_ * HD_];
__device__ float g_k_raw[BH_ * N_ * HD_];
__device__ float g_v_raw[BH_ * N_ * HD_];
__device__ float g_q[BH_ * N_ * HD_];
__device__ float g_k[BH_ * N_ * HD_];
__device__ float g_v[BH_ * N_ * HD_];
__device__ float g_relh[BH_ * N_ * H_];
__device__ float g_relw[BH_ * N_ * W_];
__device__ float g_relt[BH_ * N_ * T_];
__device__ float g_ctx[B_ * N_ * DIM_];

// ---------------- shared 64x64 NT GEMM core (K multiple of 32) -------------
// per-thread 4x4: rows m0+y+16rr, cols n0+x+16u. float4 smem, stride 36.
__device__ __forceinline__ void gemm_nt64(const float* __restrict__ A,
                                          const float* __restrict__ Bw,
                                          int K, int m0, int n0,
                                          int xx, int yy, float acc[4][4]) {
    __shared__ float Xs[64 * 36];
    __shared__ float Ws[64 * 36];
    const int tid = yy * 16 + xx;
    for (int k0 = 0; k0 < K; k0 += 32) {
        __syncthreads();
        #pragma unroll
        for (int s = 0; s < 2; s++) {
            int idx = tid + 256 * s;          // 0..511
            int r = idx >> 3, c4 = idx & 7;
            *(float4*)&Xs[r * 36 + c4 * 4] =
                *(const float4*)&A[(size_t)(m0 + r) * K + k0 + c4 * 4];
            *(float4*)&Ws[r * 36 + c4 * 4] =
                *(const float4*)&Bw[(size_t)(n0 + r) * K + k0 + c4 * 4];
        }
        __syncthreads();
        #pragma unroll
        for (int c4 = 0; c4 < 8; c4++) {
            float4 a0 = *(float4*)&Xs[(yy +  0) * 36 + c4 * 4];
            float4 a1 = *(float4*)&Xs[(yy + 16) * 36 + c4 * 4];
            float4 a2 = *(float4*)&Xs[(yy + 32) * 36 + c4 * 4];
            float4 a3 = *(float4*)&Xs[(yy + 48) * 36 + c4 * 4];
            #pragma unroll
            for (int u = 0; u < 4; u++) {
                float4 b = *(float4*)&Ws[(xx + 16 * u) * 36 + c4 * 4];
                acc[0][u] += a0.x * b.x + a0.y * b.y + a0.z * b.z + a0.w * b.w;
                acc[1][u] += a1.x * b.x + a1.y * b.y + a1.z * b.z + a1.w * b.w;
                acc[2][u] += a2.x * b.x + a2.y * b.y + a2.z * b.z + a2.w * b.w;
                acc[3][u] += a3.x * b.x + a3.y * b.y + a3.z * b.z + a3.w * b.w;
            }
        }
    }
}

// ---------------- K1: fused QKV projection, scatter to per-head buffers ----
__global__ void __launch_bounds__(256) k_qkv(const float* __restrict__ x,
                                             const float* __restrict__ qkv_w) {
    int n0 = blockIdx.x * 64, m0 = blockIdx.y * 64;
    int xx = threadIdx.x & 15, yy = threadIdx.x >> 4;
    float acc[4][4] = {};
    gemm_nt64(x, qkv_w, DIM_, m0, n0, xx, yy, acc);
    #pragma unroll
    for (int rr = 0; rr < 4; rr++) {
        int m = m0 + yy + 16 * rr;
        int b = m / N_, n = m - b * N_;
        #pragma unroll
        for (int u = 0; u < 4; u++) {
            int o = n0 + xx + 16 * u;
            int s = o / DIM_;
            int rem = o - s * DIM_;
            int head = rem / HD_;
            int c = rem - head * HD_;
            float* dst = (s == 0) ? g_q_raw : (s == 1) ? g_k_raw : g_v_raw;
            dst[((size_t)(b * NH_ + head) * N_ + n) * HD_ + c] = acc[rr][u];
        }
    }
}

// ---------------- K2: depthwise 3x3x3 conv + LayerNorm (q,k,v) ------------
__global__ void k_conv_ln(const float* __restrict__ wq, const float* __restrict__ wk,
                          const float* __restrict__ wv,
                          const float* __restrict__ gq, const float* __restrict__ bq,
                          const float* __restrict__ gk, const float* __restrict__ bk,
                          const float* __restrict__ gv, const float* __restrict__ bv) {
    int n = blockIdx.x, bh = blockIdx.y, z = blockIdx.z;
    const float* inb  = (z == 0) ? g_q_raw : (z == 1) ? g_k_raw : g_v_raw;
    float*       outb = (z == 0) ? g_q     : (z == 1) ? g_k     : g_v;
    const float* wt    = (z == 0) ? wq : (z == 1) ? wk : wv;
    const float* gamma = (z == 0) ? gq : (z == 1) ? gk : gv;
    const float* beta  = (z == 0) ? bq : (z == 1) ? bk : bv;
    int c = threadIdx.x;                 // 0..127 (96 active)
    int tt = n / (H_ * W_);
    int rem = n - tt * (H_ * W_);
    int hh = rem / W_, ww = rem - (rem / W_) * W_;

    float val = 0.f;
    if (c < HD_) {
        const float* wc = wt + c * 27;
        #pragma unroll
        for (int dt = -1; dt <= 1; dt++) {
            int t2 = tt + dt;
            if (t2 < 0 || t2 >= T_) continue;
            #pragma unroll
            for (int dh = -1; dh <= 1; dh++) {
                int h2 = hh + dh;
                if (h2 < 0 || h2 >= H_) continue;
                #pragma unroll
                for (int dw = -1; dw <= 1; dw++) {
                    int w2 = ww + dw;
                    if (w2 < 0 || w2 >= W_) continue;
                    int n2 = (t2 * H_ + h2) * W_ + w2;
                    val += wc[(dt + 1) * 9 + (dh + 1) * 3 + (dw + 1)] *
                           inb[((size_t)bh * N_ + n2) * HD_ + c];
                }
            }
        }
    }
    __shared__ float ssum[128], ssq[128];
    ssum[c] = (c < HD_) ? val : 0.f;
    ssq[c]  = (c < HD_) ? val * val : 0.f;
    __syncthreads();
    for (int s = 64; s > 0; s >>= 1) {
        if (c < s) { ssum[c] += ssum[c + s]; ssq[c] += ssq[c + s]; }
        __syncthreads();
    }
    float mean = ssum[0] * (1.f / HD_);
    float var  = ssq[0] * (1.f / HD_) - mean * mean;
    float rstd = rsqrtf(var + EPS_);
    if (c < HD_)
        outb[((size_t)bh * N_ + n) * HD_ + c] = (val - mean) * rstd * gamma[c] + beta[c];
}

// ---------------- K3: decomposed rel-pos bias projections -----------------
__global__ void k_rel(const float* __restrict__ rph, const float* __restrict__ rpw,
                      const float* __restrict__ rpt) {
    int idx = blockIdx.x * 256 + threadIdx.x;
    const int total = BH_ * N_ * 36;     // 14 + 14 + 8 outputs per (bh,i)
    if (idx >= total) return;
    int r = idx % 36;
    int bhi = idx / 36;                  // bh*N_ + i
    int i = bhi % N_;
    int it = i / (H_ * W_);
    int rem = i - it * (H_ * W_);
    int ih = rem / W_, iw = rem - (rem / W_) * W_;

    const float* qrow = g_q + (size_t)bhi * HD_;
    const float* tab;
    float* dst;
    if (r < 14)      { int k = r;      tab = rph + (ih - k + (H_ - 1)) * HD_; dst = g_relh + (size_t)bhi * H_ + k; }
    else if (r < 28) { int k = r - 14; tab = rpw + (iw - k + (W_ - 1)) * HD_; dst = g_relw + (size_t)bhi * W_ + k; }
    else             { int k = r - 28; tab = rpt + (it - k + (T_ - 1)) * HD_; dst = g_relt + (size_t)bhi * T_ + k; }
    float s = 0.f;
    #pragma unroll 8
    for (int c = 0; c < HD_; c++) s += qrow[c] * tab[c];
    *dst = s;
}

// ---------------- K4: fused flash attention ---------------------------------
// grid (49, 8): 32-row Q tile per block, 64-key chunks, online softmax.
// S tile: rows r=y+16rr (rr<2), cols j=j0+x+16u (u<4). O cols c=x*6+t (t<6).
__global__ void __launch_bounds__(256, 3) k_flash() {
    extern __shared__ float sm[];
    float* Qs = sm;            // [32][96]
    float* Ks = sm + 3072;     // [64][100]  stride 100 (==4 mod 32: bank-safe)
    float* Vs = sm + 9472;     // [64][96]
    float* Ps = sm + 15616;    // [32][64]
    float* Rh = sm + 17664;    // [32][14]
    float* Rw = sm + 18112;    // [32][14]
    float* Rt = sm + 18560;    // [32][8]

    int bh = blockIdx.y;
    int i0 = blockIdx.x * 32;
    int tid = threadIdx.x;
    int x = tid & 15, y = tid >> 4;

    const float* Qg = g_q + ((size_t)bh * N_ + i0) * HD_;
    #pragma unroll
    for (int it = 0; it < 3; it++) {
        int idx = tid + 256 * it;            // 0..767 = 32 rows x 24 float4
        int r = idx / 24, c4 = idx % 24;
        *(float4*)&Qs[r * 96 + c4 * 4] = *(const float4*)&Qg[r * 96 + c4 * 4];
    }
    for (int idx = tid; idx < 1152; idx += 256) {
        if (idx < 448)      { int r = idx / 14, k = idx - r * 14;
                              Rh[idx]        = g_relh[((size_t)bh * N_ + i0 + r) * H_ + k]; }
        else if (idx < 896) { int q = idx - 448; int r = q / 14, k = q - r * 14;
                              Rw[q]          = g_relw[((size_t)bh * N_ + i0 + r) * W_ + k]; }
        else                { int q = idx - 896; int r = q / 8, k = q - r * 8;
                              Rt[q]          = g_relt[((size_t)bh * N_ + i0 + r) * T_ + k]; }
    }

    float mrun[2] = {-1e30f, -1e30f};
    float lrun[2] = {0.f, 0.f};
    float accO[2][6] = {};

    const float* Kg = g_k + (size_t)bh * N_ * HD_;
    const float* Vg = g_v + (size_t)bh * N_ * HD_;

    for (int ch = 0; ch < 25; ch++) {
        int j0 = ch * 64;
        __syncthreads();                     // Ks/Vs free (prev GEMM2 done)
        #pragma unroll
        for (int it = 0; it < 6; it++) {
            int idx = tid + 256 * it;        // 0..1535 = 64 rows x 24 float4
            int row = idx / 24, c4 = idx % 24;
            int j = j0 + row;
            float4 kv, vv;
            if (j < N_) {
                kv = *(const float4*)&Kg[(size_t)j * 96 + c4 * 4];
                vv = *(const float4*)&Vg[(size_t)j * 96 + c4 * 4];
            } else {
                kv = make_float4(0.f, 0.f, 0.f, 0.f);
                vv = kv;
            }
            *(float4*)&Ks[row * 100 + c4 * 4] = kv;
            *(float4*)&Vs[row * 96  + c4 * 4] = vv;
        }
        __syncthreads();

        // ---- GEMM1: S = Q @ K^T ----
        float accS[2][4] = {};
        #pragma unroll 4
        for (int c4 = 0; c4 < 24; c4++) {
            float4 a0 = *(float4*)&Qs[(y +  0) * 96 + c4 * 4];
            float4 a1 = *(float4*)&Qs[(y + 16) * 96 + c4 * 4];
            #pragma unroll
            for (int u = 0; u < 4; u++) {
                float4 b = *(float4*)&Ks[(x + 16 * u) * 100 + c4 * 4];
                accS[0][u] += a0.x * b.x + a0.y * b.y + a0.z * b.z + a0.w * b.w;
                accS[1][u] += a1.x * b.x + a1.y * b.y + a1.z * b.z + a1.w * b.w;
            }
        }

        // ---- bias + online softmax ----
        #pragma unroll
        for (int rr = 0; rr < 2; rr++) {
            int r = y + 16 * rr;
            float s[4];
            float mx = -1e30f;
            #pragma unroll
            for (int u = 0; u < 4; u++) {
                int j = j0 + x + 16 * u;
                if (j < N_) {
                    int jt = j / 196;
                    int jr = j - jt * 196;
                    int jh = jr / 14;
                    int jw = jr - jh * 14;
                    s[u] = accS[rr][u] * SCALE_
                         + Rt[r * 8 + jt] + Rh[r * 14 + jh] + Rw[r * 14 + jw];
                } else s[u] = -1e30f;
                mx = fmaxf(mx, s[u]);
            }
            #pragma unroll
            for (int o = 8; o; o >>= 1) mx = fmaxf(mx, __shfl_xor_sync(0xffffffffu, mx, o));
            float mn = fmaxf(mrun[rr], mx);
            float alpha = __expf(mrun[rr] - mn);
            mrun[rr] = mn;
            float rs = 0.f;
            #pragma unroll
            for (int u = 0; u < 4; u++) {
                float p = __expf(s[u] - mn);
                rs += p;
                Ps[r * 64 + x + 16 * u] = p;
            }
            #pragma unroll
            for (int o = 8; o; o >>= 1) rs += __shfl_xor_sync(0xffffffffu, rs, o);
            lrun[rr] = lrun[rr] * alpha + rs;
            #pragma unroll
            for (int t = 0; t < 6; t++) accO[rr][t] *= alpha;
        }
        __syncthreads();

        // ---- GEMM2: O += P @ V ----
        #pragma unroll 4
        for (int j4 = 0; j4 < 16; j4++) {
            float4 p0 = *(float4*)&Ps[(y +  0) * 64 + j4 * 4];
            float4 p1 = *(float4*)&Ps[(y + 16) * 64 + j4 * 4];
            float pa0[4] = {p0.x, p0.y, p0.z, p0.w};
            float pa1[4] = {p1.x, p1.y, p1.z, p1.w};
            #pragma unroll
            for (int jj = 0; jj < 4; jj++) {
                const float* vb = &Vs[(j4 * 4 + jj) * 96 + x * 6];
                float2 v0 = *(const float2*)(vb + 0);
                float2 v1 = *(const float2*)(vb + 2);
                float2 v2 = *(const float2*)(vb + 4);
                accO[0][0] += pa0[jj] * v0.x;  accO[0][1] += pa0[jj] * v0.y;
                accO[0][2] += pa0[jj] * v1.x;  accO[0][3] += pa0[jj] * v1.y;
                accO[0][4] += pa0[jj] * v2.x;  accO[0][5] += pa0[jj] * v2.y;
                accO[1][0] += pa1[jj] * v0.x;  accO[1][1] += pa1[jj] * v0.y;
                accO[1][2] += pa1[jj] * v1.x;  accO[1][3] += pa1[jj] * v1.y;
                accO[1][4] += pa1[jj] * v2.x;  accO[1][5] += pa1[jj] * v2.y;
            }
        }
    }

    // ---- epilogue: O/l + residual q, interleave heads into g_ctx ----
    int b = bh >> 2, nh = bh & 3;
    #pragma unroll
    for (int rr = 0; rr < 2; rr++) {
        int r = y + 16 * rr;
        int i = i0 + r;
        float inv = 1.f / lrun[rr];
        float* dst = &g_ctx[(((size_t)b * N_ + i) * NH_ + nh) * HD_ + x * 6];
        const float* qrow = &Qs[r * 96 + x * 6];
        #pragma unroll
        for (int t = 0; t < 6; t++)
            dst[t] = accO[rr][t] * inv + qrow[t];
    }
}

// ---------------- K5: output projection + bias -----------------------------
__global__ void __launch_bounds__(256) k_proj(const float* __restrict__ proj_w,
                                              const float* __restrict__ proj_b,
                                              float* __restrict__ out) {
    int n0 = blockIdx.x * 64, m0 = blockIdx.y * 64;
    int xx = threadIdx.x & 15, yy = threadIdx.x >> 4;
    float acc[4][4] = {};
    gemm_nt64(g_ctx, proj_w, DIM_, m0, n0, xx, yy, acc);
    #pragma unroll
    for (int rr = 0; rr < 4; rr++) {
        int m = m0 + yy + 16 * rr;
        #pragma unroll
        for (int u = 0; u < 4; u++) {
            int o = n0 + xx + 16 * u;
            out[(size_t)m * DIM_ + o] = acc[rr][u] + proj_b[o];
        }
    }
}

// ---------------- launch ----------------------------------------------------
extern "C" void kernel_launch(void* const* d_in, const int* in_sizes, int n_in,
                              void* d_out, int out_size) {
    const float* x      = (const float*)d_in[0];
    const float* qkv_w  = (const float*)d_in[1];
    const float* proj_w = (const float*)d_in[2];
    const float* proj_b = (const float*)d_in[3];
    const float* pqw    = (const float*)d_in[4];
    const float* pkw    = (const float*)d_in[5];
    const float* pvw    = (const float*)d_in[6];
    const float* nqw    = (const float*)d_in[7];
    const float* nqb    = (const float*)d_in[8];
    const float* nkw    = (const float*)d_in[9];
    const float* nkb    = (const float*)d_in[10];
    const float* nvw    = (const float*)d_in[11];
    const float* nvb    = (const float*)d_in[12];
    const float* rph    = (const float*)d_in[13];
    const float* rpw    = (const float*)d_in[14];
    const float* rpt    = (const float*)d_in[15];
    float* out = (float*)d_out;

    cudaFuncSetAttribute(k_flash, cudaFuncAttributeMaxDynamicSharedMemorySize, 75264);

    k_qkv<<<dim3(18, 49), 256>>>(x, qkv_w);
    k_conv_ln<<<dim3(N_, BH_, 3), 128>>>(pqw, pkw, pvw, nqw, nqb, nkw, nkb, nvw, nvb);
    k_rel<<<(BH_ * N_ * 36 + 255) / 256, 256>>>(rph, rpw, rpt);
    k_flash<<<dim3(49, BH_), 256, 75264>>>();
    k_proj<<<dim3(6, 49), 256>>>(proj_w, proj_b, out);
}

// round 3
// speedup vs baseline: 1.3212x; 1.1724x over previous
#include <cuda_runtime.h>
#include <cuda_bf16.h>
#include <math.h>

#define B_    2
#define NH_   4
#define T_    8
#define H_    14
#define W_    14
#define N_    1568
#define DIM_  384
#define HD_   96
#define BH_   (B_*NH_)
#define M_    (B_*N_)
#define EPS_  1e-6f
#define SCALE_ 0.1020620726159657f   // 96^-0.5

typedef unsigned long long ull;

// ---- packed f32x2 helpers (FFMA2: PTX-only, ptxas never emits it) --------
__device__ __forceinline__ void fma2(ull& d, ull a, ull b) {
    asm("fma.rn.f32x2 %0, %1, %2, %0;" : "+l"(d) : "l"(a), "l"(b));
}
__device__ __forceinline__ void mul2(ull& d, ull a) {
    asm("mul.rn.f32x2 %0, %0, %1;" : "+l"(d) : "l"(a));
}
__device__ __forceinline__ float hadd2(ull v) {
    float lo, hi;
    asm("mov.b64 {%0, %1}, %2;" : "=f"(lo), "=f"(hi) : "l"(v));
    return lo + hi;
}
__device__ __forceinline__ ull dup2(float f) {
    ull d;
    asm("mov.b64 %0, {%1, %1};" : "=l"(d) : "f"(f));
    return d;
}
__device__ __forceinline__ void unpack2(ull v, float& lo, float& hi) {
    asm("mov.b64 {%0, %1}, %2;" : "=f"(lo), "=f"(hi) : "l"(v));
}

// ---------------- scratch ---------------------------------------------------
__device__ float g_q_raw[BH_ * N_ * HD_];
__device__ float g_k_raw[BH_ * N_ * HD_];
__device__ float g_v_raw[BH_ * N_ * HD_];
__device__ float g_q[BH_ * N_ * HD_];
__device__ float g_k[BH_ * N_ * HD_];
__device__ float g_v[BH_ * N_ * HD_];
__device__ float g_relh[BH_ * N_ * H_];
__device__ float g_relw[BH_ * N_ * W_];
__device__ float g_relt[BH_ * N_ * T_];
__device__ float g_ctx[B_ * N_ * DIM_];

// ---------------- 64x64 NT GEMM core, packed-k FFMA2 -----------------------
__device__ __forceinline__ void gemm_nt64(const float* __restrict__ A,
                                          const float* __restrict__ Bw,
                                          int K, int m0, int n0,
                                          int xx, int yy, ull acc2[4][4]) {
    __shared__ float Xs[64 * 36];
    __shared__ float Ws[64 * 36];
    const int tid = yy * 16 + xx;
    for (int k0 = 0; k0 < K; k0 += 32) {
        __syncthreads();
        #pragma unroll
        for (int s = 0; s < 2; s++) {
            int idx = tid + 256 * s;
            int r = idx >> 3, c4 = idx & 7;
            *(float4*)&Xs[r * 36 + c4 * 4] =
                *(const float4*)&A[(size_t)(m0 + r) * K + k0 + c4 * 4];
            *(float4*)&Ws[r * 36 + c4 * 4] =
                *(const float4*)&Bw[(size_t)(n0 + r) * K + k0 + c4 * 4];
        }
        __syncthreads();
        #pragma unroll
        for (int c4 = 0; c4 < 8; c4++) {
            ulonglong2 a[4];
            #pragma unroll
            for (int rr = 0; rr < 4; rr++)
                a[rr] = *(ulonglong2*)&Xs[(yy + 16 * rr) * 36 + c4 * 4];
            #pragma unroll
            for (int u = 0; u < 4; u++) {
                ulonglong2 b = *(ulonglong2*)&Ws[(xx + 16 * u) * 36 + c4 * 4];
                #pragma unroll
                for (int rr = 0; rr < 4; rr++) {
                    fma2(acc2[rr][u], a[rr].x, b.x);
                    fma2(acc2[rr][u], a[rr].y, b.y);
                }
            }
        }
    }
}

// ---------------- K1: QKV projection ---------------------------------------
__global__ void __launch_bounds__(256) k_qkv(const float* __restrict__ x,
                                             const float* __restrict__ qkv_w) {
    int n0 = blockIdx.x * 64, m0 = blockIdx.y * 64;
    int xx = threadIdx.x & 15, yy = threadIdx.x >> 4;
    ull acc2[4][4] = {};
    gemm_nt64(x, qkv_w, DIM_, m0, n0, xx, yy, acc2);
    #pragma unroll
    for (int rr = 0; rr < 4; rr++) {
        int m = m0 + yy + 16 * rr;
        int b = m / N_, n = m - b * N_;
        #pragma unroll
        for (int u = 0; u < 4; u++) {
            int o = n0 + xx + 16 * u;
            int s = o / DIM_;
            int rem = o - s * DIM_;
            int head = rem / HD_;
            int c = rem - head * HD_;
            float* dst = (s == 0) ? g_q_raw : (s == 1) ? g_k_raw : g_v_raw;
            dst[((size_t)(b * NH_ + head) * N_ + n) * HD_ + c] = hadd2(acc2[rr][u]);
        }
    }
}

// ---------------- K2: conv3x3x3 + LayerNorm, warp per token ---------------
__global__ void __launch_bounds__(128) k_conv_ln(
        const float* __restrict__ wq, const float* __restrict__ wk,
        const float* __restrict__ wv,
        const float* __restrict__ gq, const float* __restrict__ bq,
        const float* __restrict__ gk, const float* __restrict__ bk,
        const float* __restrict__ gv, const float* __restrict__ bv) {
    int gid = blockIdx.x * 4 + (threadIdx.x >> 5);
    int lane = threadIdx.x & 31;
    int z = gid / (BH_ * N_);
    int rem0 = gid - z * (BH_ * N_);
    int bh = rem0 / N_;
    int n = rem0 - bh * N_;
    const float* inb  = (z == 0) ? g_q_raw : (z == 1) ? g_k_raw : g_v_raw;
    float*       outb = (z == 0) ? g_q     : (z == 1) ? g_k     : g_v;
    const float* wt    = (z == 0) ? wq : (z == 1) ? wk : wv;
    const float* gamma = (z == 0) ? gq : (z == 1) ? gk : gv;
    const float* beta  = (z == 0) ? bq : (z == 1) ? bk : bv;

    int tt = n / (H_ * W_);
    int rem = n - tt * (H_ * W_);
    int hh = rem / W_, ww = rem - (rem / W_) * W_;

    float val[3] = {0.f, 0.f, 0.f};
    #pragma unroll
    for (int dt = -1; dt <= 1; dt++) {
        int t2 = tt + dt;
        if (t2 < 0 || t2 >= T_) continue;
        #pragma unroll
        for (int dh = -1; dh <= 1; dh++) {
            int h2 = hh + dh;
            if (h2 < 0 || h2 >= H_) continue;
            #pragma unroll
            for (int dw = -1; dw <= 1; dw++) {
                int w2 = ww + dw;
                if (w2 < 0 || w2 >= W_) continue;
                int n2 = (t2 * H_ + h2) * W_ + w2;
                const float* src = &inb[((size_t)bh * N_ + n2) * HD_];
                int tap = (dt + 1) * 9 + (dh + 1) * 3 + (dw + 1);
                #pragma unroll
                for (int p = 0; p < 3; p++) {
                    int c = lane + 32 * p;
                    val[p] += wt[c * 27 + tap] * src[c];
                }
            }
        }
    }
    float s = val[0] + val[1] + val[2];
    float q = val[0]*val[0] + val[1]*val[1] + val[2]*val[2];
    #pragma unroll
    for (int o = 16; o; o >>= 1) {
        s += __shfl_xor_sync(0xffffffffu, s, o);
        q += __shfl_xor_sync(0xffffffffu, q, o);
    }
    float mean = s * (1.f / HD_);
    float var  = q * (1.f / HD_) - mean * mean;
    float rstd = rsqrtf(var + EPS_);
    float* dst = &outb[((size_t)bh * N_ + n) * HD_];
    #pragma unroll
    for (int p = 0; p < 3; p++) {
        int c = lane + 32 * p;
        dst[c] = (val[p] - mean) * rstd * gamma[c] + beta[c];
    }
}

// ---------------- K3: decomposed rel-pos bias projections -----------------
__global__ void k_rel(const float* __restrict__ rph, const float* __restrict__ rpw,
                      const float* __restrict__ rpt) {
    int idx = blockIdx.x * 256 + threadIdx.x;
    const int total = BH_ * N_ * 36;
    if (idx >= total) return;
    int r = idx % 36;
    int bhi = idx / 36;
    int i = bhi % N_;
    int it = i / (H_ * W_);
    int rem = i - it * (H_ * W_);
    int ih = rem / W_, iw = rem - (rem / W_) * W_;

    const float* qrow = g_q + (size_t)bhi * HD_;
    const float* tab;
    float* dst;
    if (r < 14)      { int k = r;      tab = rph + (ih - k + (H_ - 1)) * HD_; dst = g_relh + (size_t)bhi * H_ + k; }
    else if (r < 28) { int k = r - 14; tab = rpw + (iw - k + (W_ - 1)) * HD_; dst = g_relw + (size_t)bhi * W_ + k; }
    else             { int k = r - 28; tab = rpt + (it - k + (T_ - 1)) * HD_; dst = g_relt + (size_t)bhi * T_ + k; }
    float s = 0.f;
    #pragma unroll 8
    for (int c = 0; c < HD_; c++) s += qrow[c] * tab[c];
    *dst = s;
}

// ---------------- K4: fused flash attention, 128 thr, FFMA2 ----------------
// 32 Q rows/block, 64-key chunks. x=tid&15, y=tid>>4; rows y+8rr, S cols x+16u,
// O cols x*6+t. Packed: GEMM1 along k, GEMM2 along output cols.
__global__ void __launch_bounds__(128, 3) k_flash() {
    extern __shared__ float sm[];
    float* Qs = sm;            // [32][96]
    float* Ks = sm + 3072;     // [64][100]
    float* Vs = sm + 9472;     // [64][96]
    float* Ps = sm + 15616;    // [32][68]
    float* Rh = sm + 17792;    // [32][14]
    float* Rw = sm + 18240;    // [32][14]
    float* Rt = sm + 18688;    // [32][8]

    int bh = blockIdx.y;
    int i0 = blockIdx.x * 32;
    int tid = threadIdx.x;
    int x = tid & 15, y = tid >> 4;

    const float* Qg = g_q + ((size_t)bh * N_ + i0) * HD_;
    #pragma unroll
    for (int it = 0; it < 6; it++) {
        int idx = tid + 128 * it;            // 768 = 32 rows x 24 float4
        int r = idx / 24, c4 = idx % 24;
        *(float4*)&Qs[r * 96 + c4 * 4] = *(const float4*)&Qg[r * 96 + c4 * 4];
    }
    for (int idx = tid; idx < 1152; idx += 128) {
        if (idx < 448)      { int r = idx / 14, k = idx - r * 14;
                              Rh[idx]  = g_relh[((size_t)bh * N_ + i0 + r) * H_ + k]; }
        else if (idx < 896) { int q = idx - 448; int r = q / 14, k = q - r * 14;
                              Rw[q]    = g_relw[((size_t)bh * N_ + i0 + r) * W_ + k]; }
        else                { int q = idx - 896; int r = q / 8, k = q - r * 8;
                              Rt[q]    = g_relt[((size_t)bh * N_ + i0 + r) * T_ + k]; }
    }

    float mrun[4] = {-1e30f, -1e30f, -1e30f, -1e30f};
    float lrun[4] = {0.f, 0.f, 0.f, 0.f};
    ull accO2[4][3] = {};                    // f32x2 pairs over col pairs

    const float* Kg = g_k + (size_t)bh * N_ * HD_;
    const float* Vg = g_v + (size_t)bh * N_ * HD_;

    for (int ch = 0; ch < 25; ch++) {
        int j0 = ch * 64;
        __syncthreads();
        #pragma unroll
        for (int it = 0; it < 12; it++) {
            int idx = tid + 128 * it;        // 1536 = 64 rows x 24 float4
            int row = idx / 24, c4 = idx % 24;
            int j = j0 + row;
            float4 kv, vv;
            if (j < N_) {
                kv = *(const float4*)&Kg[(size_t)j * 96 + c4 * 4];
                vv = *(const float4*)&Vg[(size_t)j * 96 + c4 * 4];
            } else {
                kv = make_float4(0.f, 0.f, 0.f, 0.f);
                vv = kv;
            }
            *(float4*)&Ks[row * 100 + c4 * 4] = kv;
            *(float4*)&Vs[row * 96  + c4 * 4] = vv;
        }
        __syncthreads();

        // ---- GEMM1: S = Q @ K^T (packed along k) ----
        ull accS2[4][4] = {};
        #pragma unroll 6
        for (int c4 = 0; c4 < 24; c4++) {
            ulonglong2 a[4];
            #pragma unroll
            for (int rr = 0; rr < 4; rr++)
                a[rr] = *(ulonglong2*)&Qs[(y + 8 * rr) * 96 + c4 * 4];
            #pragma unroll
            for (int u = 0; u < 4; u++) {
                ulonglong2 b = *(ulonglong2*)&Ks[(x + 16 * u) * 100 + c4 * 4];
                #pragma unroll
                for (int rr = 0; rr < 4; rr++) {
                    fma2(accS2[rr][u], a[rr].x, b.x);
                    fma2(accS2[rr][u], a[rr].y, b.y);
                }
            }
        }

        // ---- bias + online softmax ----
        #pragma unroll
        for (int rr = 0; rr < 4; rr++) {
            int r = y + 8 * rr;
            float s[4];
            float mx = -1e30f;
            #pragma unroll
            for (int u = 0; u < 4; u++) {
                int j = j0 + x + 16 * u;
                if (j < N_) {
                    int jt = j / 196;
                    int jr = j - jt * 196;
                    int jh = jr / 14;
                    int jw = jr - jh * 14;
                    s[u] = hadd2(accS2[rr][u]) * SCALE_
                         + Rt[r * 8 + jt] + Rh[r * 14 + jh] + Rw[r * 14 + jw];
                } else s[u] = -1e30f;
                mx = fmaxf(mx, s[u]);
            }
            #pragma unroll
            for (int o = 8; o; o >>= 1) mx = fmaxf(mx, __shfl_xor_sync(0xffffffffu, mx, o));
            float mn = fmaxf(mrun[rr], mx);
            float alpha = __expf(mrun[rr] - mn);
            mrun[rr] = mn;
            float rs = 0.f;
            #pragma unroll
            for (int u = 0; u < 4; u++) {
                float p = __expf(s[u] - mn);
                rs += p;
                Ps[r * 68 + x + 16 * u] = p;
            }
            #pragma unroll
            for (int o = 8; o; o >>= 1) rs += __shfl_xor_sync(0xffffffffu, rs, o);
            lrun[rr] = lrun[rr] * alpha + rs;
            ull al2 = dup2(alpha);
            mul2(accO2[rr][0], al2);
            mul2(accO2[rr][1], al2);
            mul2(accO2[rr][2], al2);
        }
        __syncthreads();

        // ---- GEMM2: O += P @ V (packed along output cols) ----
        #pragma unroll 4
        for (int j4 = 0; j4 < 16; j4++) {
            float4 p[4];
            #pragma unroll
            for (int rr = 0; rr < 4; rr++)
                p[rr] = *(float4*)&Ps[(y + 8 * rr) * 68 + j4 * 4];
            #pragma unroll
            for (int jj = 0; jj < 4; jj++) {
                const float* vb = &Vs[(j4 * 4 + jj) * 96 + x * 6];
                ull v0 = *(const ull*)(vb + 0);
                ull v1 = *(const ull*)(vb + 2);
                ull v2 = *(const ull*)(vb + 4);
                #pragma unroll
                for (int rr = 0; rr < 4; rr++) {
                    float pv = (jj == 0) ? p[rr].x : (jj == 1) ? p[rr].y
                             : (jj == 2) ? p[rr].z : p[rr].w;
                    ull pd = dup2(pv);
                    fma2(accO2[rr][0], pd, v0);
                    fma2(accO2[rr][1], pd, v1);
                    fma2(accO2[rr][2], pd, v2);
                }
            }
        }
    }

    // ---- epilogue ----
    int b = bh >> 2, nh = bh & 3;
    #pragma unroll
    for (int rr = 0; rr < 4; rr++) {
        int r = y + 8 * rr;
        int i = i0 + r;
        float inv = 1.f / lrun[rr];
        float* dst = &g_ctx[(((size_t)b * N_ + i) * NH_ + nh) * HD_ + x * 6];
        const float* qrow = &Qs[r * 96 + x * 6];
        #pragma unroll
        for (int tp = 0; tp < 3; tp++) {
            float lo, hi;
            unpack2(accO2[rr][tp], lo, hi);
            dst[2 * tp + 0] = lo * inv + qrow[2 * tp + 0];
            dst[2 * tp + 1] = hi * inv + qrow[2 * tp + 1];
        }
    }
}

// ---------------- K5: output projection + bias -----------------------------
__global__ void __launch_bounds__(256) k_proj(const float* __restrict__ proj_w,
                                              const float* __restrict__ proj_b,
                                              float* __restrict__ out) {
    int n0 = blockIdx.x * 64, m0 = blockIdx.y * 64;
    int xx = threadIdx.x & 15, yy = threadIdx.x >> 4;
    ull acc2[4][4] = {};
    gemm_nt64(g_ctx, proj_w, DIM_, m0, n0, xx, yy, acc2);
    #pragma unroll
    for (int rr = 0; rr < 4; rr++) {
        int m = m0 + yy + 16 * rr;
        #pragma unroll
        for (int u = 0; u < 4; u++) {
            int o = n0 + xx + 16 * u;
            out[(size_t)m * DIM_ + o] = hadd2(acc2[rr][u]) + proj_b[o];
        }
    }
}

// ---------------- launch ----------------------------------------------------
extern "C" void kernel_launch(void* const* d_in, const int* in_sizes, int n_in,
                              void* d_out, int out_size) {
    const float* x      = (const float*)d_in[0];
    const float* qkv_w  = (const float*)d_in[1];
    const float* proj_w = (const float*)d_in[2];
    const float* proj_b = (const float*)d_in[3];
    const float* pqw    = (const float*)d_in[4];
    const float* pkw    = (const float*)d_in[5];
    const float* pvw    = (const float*)d_in[6];
    const float* nqw    = (const float*)d_in[7];
    const float* nqb    = (const float*)d_in[8];
    const float* nkw    = (const float*)d_in[9];
    const float* nkb    = (const float*)d_in[10];
    const float* nvw    = (const float*)d_in[11];
    const float* nvb    = (const float*)d_in[12];
    const float* rph    = (const float*)d_in[13];
    const float* rpw    = (const float*)d_in[14];
    const float* rpt    = (const float*)d_in[15];
    float* out = (float*)d_out;

    cudaFuncSetAttribute(k_flash, cudaFuncAttributeMaxDynamicSharedMemorySize, 75776);

    k_qkv<<<dim3(18, 49), 256>>>(x, qkv_w);
    k_conv_ln<<<(BH_ * N_ * 3) / 4, 128>>>(pqw, pkw, pvw, nqw, nqb, nkw, nkb, nvw, nvb);
    k_rel<<<(BH_ * N_ * 36 + 255) / 256, 256>>>(rph, rpw, rpt);
    k_flash<<<dim3(49, BH_), 128, 75776>>>();
    k_proj<<<dim3(6, 49), 256>>>(proj_w, proj_b, out);
}

// round 4
// speedup vs baseline: 1.4078x; 1.0656x over previous
#include <cuda_runtime.h>
#include <cuda_bf16.h>
#include <math.h>

#define B_    2
#define NH_   4
#define T_    8
#define H_    14
#define W_    14
#define N_    1568
#define DIM_  384
#define HD_   96
#define BH_   (B_*NH_)
#define M_    (B_*N_)
#define EPS_  1e-6f
#define SCALE_ 0.1020620726159657f   // 96^-0.5

typedef unsigned long long ull;

// ---- packed f32x2 helpers (FFMA2: PTX-only) ------------------------------
__device__ __forceinline__ void fma2(ull& d, ull a, ull b) {
    asm("fma.rn.f32x2 %0, %1, %2, %0;" : "+l"(d) : "l"(a), "l"(b));
}
__device__ __forceinline__ void mul2(ull& d, ull a) {
    asm("mul.rn.f32x2 %0, %0, %1;" : "+l"(d) : "l"(a));
}
__device__ __forceinline__ float hadd2(ull v) {
    float lo, hi;
    asm("mov.b64 {%0, %1}, %2;" : "=f"(lo), "=f"(hi) : "l"(v));
    return lo + hi;
}
__device__ __forceinline__ ull dup2(float f) {
    ull d;
    asm("mov.b64 %0, {%1, %1};" : "=l"(d) : "f"(f));
    return d;
}
__device__ __forceinline__ void unpack2(ull v, float& lo, float& hi) {
    asm("mov.b64 {%0, %1}, %2;" : "=f"(lo), "=f"(hi) : "l"(v));
}

// ---------------- scratch ---------------------------------------------------
__device__ float g_q_raw[BH_ * N_ * HD_];
__device__ float g_k_raw[BH_ * N_ * HD_];
__device__ float g_v_raw[BH_ * N_ * HD_];
__device__ float g_q[BH_ * N_ * HD_];
__device__ float g_k[BH_ * N_ * HD_];
__device__ float g_v[BH_ * N_ * HD_];
__device__ float g_ctx[B_ * N_ * DIM_];

// ---------------- 64x64 NT GEMM core, packed-k FFMA2 -----------------------
__device__ __forceinline__ void gemm_nt64(const float* __restrict__ A,
                                          const float* __restrict__ Bw,
                                          int K, int m0, int n0,
                                          int xx, int yy, ull acc2[4][4]) {
    __shared__ float Xs[64 * 36];
    __shared__ float Ws[64 * 36];
    const int tid = yy * 16 + xx;
    for (int k0 = 0; k0 < K; k0 += 32) {
        __syncthreads();
        #pragma unroll
        for (int s = 0; s < 2; s++) {
            int idx = tid + 256 * s;
            int r = idx >> 3, c4 = idx & 7;
            *(float4*)&Xs[r * 36 + c4 * 4] =
                *(const float4*)&A[(size_t)(m0 + r) * K + k0 + c4 * 4];
            *(float4*)&Ws[r * 36 + c4 * 4] =
                *(const float4*)&Bw[(size_t)(n0 + r) * K + k0 + c4 * 4];
        }
        __syncthreads();
        #pragma unroll
        for (int c4 = 0; c4 < 8; c4++) {
            ulonglong2 a[4];
            #pragma unroll
            for (int rr = 0; rr < 4; rr++)
                a[rr] = *(ulonglong2*)&Xs[(yy + 16 * rr) * 36 + c4 * 4];
            #pragma unroll
            for (int u = 0; u < 4; u++) {
                ulonglong2 b = *(ulonglong2*)&Ws[(xx + 16 * u) * 36 + c4 * 4];
                #pragma unroll
                for (int rr = 0; rr < 4; rr++) {
                    fma2(acc2[rr][u], a[rr].x, b.x);
                    fma2(acc2[rr][u], a[rr].y, b.y);
                }
            }
        }
    }
}

// ---------------- K1: QKV projection ---------------------------------------
__global__ void __launch_bounds__(256) k_qkv(const float* __restrict__ x,
                                             const float* __restrict__ qkv_w) {
    int n0 = blockIdx.x * 64, m0 = blockIdx.y * 64;
    int xx = threadIdx.x & 15, yy = threadIdx.x >> 4;
    ull acc2[4][4] = {};
    gemm_nt64(x, qkv_w, DIM_, m0, n0, xx, yy, acc2);
    #pragma unroll
    for (int rr = 0; rr < 4; rr++) {
        int m = m0 + yy + 16 * rr;
        int b = m / N_, n = m - b * N_;
        #pragma unroll
        for (int u = 0; u < 4; u++) {
            int o = n0 + xx + 16 * u;
            int s = o / DIM_;
            int rem = o - s * DIM_;
            int head = rem / HD_;
            int c = rem - head * HD_;
            float* dst = (s == 0) ? g_q_raw : (s == 1) ? g_k_raw : g_v_raw;
            dst[((size_t)(b * NH_ + head) * N_ + n) * HD_ + c] = hadd2(acc2[rr][u]);
        }
    }
}

// ---------------- K2: conv3x3x3 + LayerNorm, warp per token ---------------
__global__ void __launch_bounds__(128) k_conv_ln(
        const float* __restrict__ wq, const float* __restrict__ wk,
        const float* __restrict__ wv,
        const float* __restrict__ gq, const float* __restrict__ bq,
        const float* __restrict__ gk, const float* __restrict__ bk,
        const float* __restrict__ gv, const float* __restrict__ bv) {
    int gid = blockIdx.x * 4 + (threadIdx.x >> 5);
    int lane = threadIdx.x & 31;
    int z = gid / (BH_ * N_);
    int rem0 = gid - z * (BH_ * N_);
    int bh = rem0 / N_;
    int n = rem0 - bh * N_;
    const float* inb  = (z == 0) ? g_q_raw : (z == 1) ? g_k_raw : g_v_raw;
    float*       outb = (z == 0) ? g_q     : (z == 1) ? g_k     : g_v;
    const float* wt    = (z == 0) ? wq : (z == 1) ? wk : wv;
    const float* gamma = (z == 0) ? gq : (z == 1) ? gk : gv;
    const float* beta  = (z == 0) ? bq : (z == 1) ? bk : bv;

    int tt = n / (H_ * W_);
    int rem = n - tt * (H_ * W_);
    int hh = rem / W_, ww = rem - (rem / W_) * W_;

    float val[3] = {0.f, 0.f, 0.f};
    #pragma unroll
    for (int dt = -1; dt <= 1; dt++) {
        int t2 = tt + dt;
        if (t2 < 0 || t2 >= T_) continue;
        #pragma unroll
        for (int dh = -1; dh <= 1; dh++) {
            int h2 = hh + dh;
            if (h2 < 0 || h2 >= H_) continue;
            #pragma unroll
            for (int dw = -1; dw <= 1; dw++) {
                int w2 = ww + dw;
                if (w2 < 0 || w2 >= W_) continue;
                int n2 = (t2 * H_ + h2) * W_ + w2;
                const float* src = &inb[((size_t)bh * N_ + n2) * HD_];
                int tap = (dt + 1) * 9 + (dh + 1) * 3 + (dw + 1);
                #pragma unroll
                for (int p = 0; p < 3; p++) {
                    int c = lane + 32 * p;
                    val[p] += wt[c * 27 + tap] * src[c];
                }
            }
        }
    }
    float s = val[0] + val[1] + val[2];
    float q = val[0]*val[0] + val[1]*val[1] + val[2]*val[2];
    #pragma unroll
    for (int o = 16; o; o >>= 1) {
        s += __shfl_xor_sync(0xffffffffu, s, o);
        q += __shfl_xor_sync(0xffffffffu, q, o);
    }
    float mean = s * (1.f / HD_);
    float var  = q * (1.f / HD_) - mean * mean;
    float rstd = rsqrtf(var + EPS_);
    float* dst = &outb[((size_t)bh * N_ + n) * HD_];
    #pragma unroll
    for (int p = 0; p < 3; p++) {
        int c = lane + 32 * p;
        dst[c] = (val[p] - mean) * rstd * gamma[c] + beta[c];
    }
}

// ---------------- K3: fused flash attention, 256 thr, FFMA2 ----------------
// 32 Q rows/block, 64-key chunks. Rel-pos dots computed in prologue from Qs.
// x=tid&15, y=tid>>4 (0..15); rows y+16rr (rr<2), S cols x+16u, O cols x*6+t.
__global__ void __launch_bounds__(256, 3) k_flash(const float* __restrict__ rph,
                                                  const float* __restrict__ rpw,
                                                  const float* __restrict__ rpt) {
    extern __shared__ float sm[];
    float* Qs = sm;            // [32][96]
    float* Ks = sm + 3072;     // [64][100]
    float* Vs = sm + 9472;     // [64][96]
    float* Ps = sm + 15616;    // [32][68]
    float* Rh = sm + 17792;    // [32][14]
    float* Rw = sm + 18240;    // [32][14]
    float* Rt = sm + 18688;    // [32][8]

    int bh = blockIdx.y;
    int i0 = blockIdx.x * 32;
    int tid = threadIdx.x;
    int x = tid & 15, y = tid >> 4;

    const float* Qg = g_q + ((size_t)bh * N_ + i0) * HD_;
    #pragma unroll
    for (int it = 0; it < 3; it++) {
        int idx = tid + 256 * it;            // 768 = 32 rows x 24 float4
        int r = idx / 24, c4 = idx % 24;
        *(float4*)&Qs[r * 96 + c4 * 4] = *(const float4*)&Qg[r * 96 + c4 * 4];
    }
    __syncthreads();

    // ---- rel-pos bias dots from Qs (replaces separate k_rel kernel) ----
    #pragma unroll
    for (int idx = tid; idx < 1152; idx += 256) {
        int r = idx / 36, e = idx - (idx / 36) * 36;
        int i = i0 + r;
        int it = i / 196;
        int rm = i - it * 196;
        int ih = rm / 14, iw = rm - ih * 14;
        const float* tab;
        float* dst;
        if (e < 14)      { tab = rph + (ih - e + 13) * HD_;        dst = &Rh[r * 14 + e]; }
        else if (e < 28) { int k = e - 14; tab = rpw + (iw - k + 13) * HD_; dst = &Rw[r * 14 + k]; }
        else             { int k = e - 28; tab = rpt + (it - k + 7) * HD_;  dst = &Rt[r * 8 + k]; }
        float s = 0.f;
        #pragma unroll 6
        for (int c4 = 0; c4 < 24; c4++) {
            float4 a = *(float4*)&Qs[r * 96 + c4 * 4];
            float4 b = *(const float4*)&tab[c4 * 4];
            s += a.x * b.x + a.y * b.y + a.z * b.z + a.w * b.w;
        }
        *dst = s;
    }

    float mrun[2] = {-1e30f, -1e30f};
    float lrun[2] = {0.f, 0.f};
    ull accO2[2][3] = {};

    const float* Kg = g_k + (size_t)bh * N_ * HD_;
    const float* Vg = g_v + (size_t)bh * N_ * HD_;

    for (int ch = 0; ch < 25; ch++) {
        int j0 = ch * 64;
        __syncthreads();
        #pragma unroll
        for (int it = 0; it < 6; it++) {
            int idx = tid + 256 * it;        // 1536 = 64 rows x 24 float4
            int row = idx / 24, c4 = idx % 24;
            int j = j0 + row;
            float4 kv, vv;
            if (j < N_) {
                kv = *(const float4*)&Kg[(size_t)j * 96 + c4 * 4];
                vv = *(const float4*)&Vg[(size_t)j * 96 + c4 * 4];
            } else {
                kv = make_float4(0.f, 0.f, 0.f, 0.f);
                vv = kv;
            }
            *(float4*)&Ks[row * 100 + c4 * 4] = kv;
            *(float4*)&Vs[row * 96  + c4 * 4] = vv;
        }
        __syncthreads();

        // ---- GEMM1: S = Q @ K^T (packed along k) ----
        ull accS2[2][4] = {};
        #pragma unroll 6
        for (int c4 = 0; c4 < 24; c4++) {
            ulonglong2 a0 = *(ulonglong2*)&Qs[(y +  0) * 96 + c4 * 4];
            ulonglong2 a1 = *(ulonglong2*)&Qs[(y + 16) * 96 + c4 * 4];
            #pragma unroll
            for (int u = 0; u < 4; u++) {
                ulonglong2 b = *(ulonglong2*)&Ks[(x + 16 * u) * 100 + c4 * 4];
                fma2(accS2[0][u], a0.x, b.x);
                fma2(accS2[0][u], a0.y, b.y);
                fma2(accS2[1][u], a1.x, b.x);
                fma2(accS2[1][u], a1.y, b.y);
            }
        }

        // ---- bias + online softmax ----
        #pragma unroll
        for (int rr = 0; rr < 2; rr++) {
            int r = y + 16 * rr;
            float s[4];
            float mx = -1e30f;
            #pragma unroll
            for (int u = 0; u < 4; u++) {
                int j = j0 + x + 16 * u;
                if (j < N_) {
                    int jt = j / 196;
                    int jr = j - jt * 196;
                    int jh = jr / 14;
                    int jw = jr - jh * 14;
                    s[u] = hadd2(accS2[rr][u]) * SCALE_
                         + Rt[r * 8 + jt] + Rh[r * 14 + jh] + Rw[r * 14 + jw];
                } else s[u] = -1e30f;
                mx = fmaxf(mx, s[u]);
            }
            #pragma unroll
            for (int o = 8; o; o >>= 1) mx = fmaxf(mx, __shfl_xor_sync(0xffffffffu, mx, o));
            float mn = fmaxf(mrun[rr], mx);
            float alpha = __expf(mrun[rr] - mn);
            mrun[rr] = mn;
            float rs = 0.f;
            #pragma unroll
            for (int u = 0; u < 4; u++) {
                float p = __expf(s[u] - mn);
                rs += p;
                Ps[r * 68 + x + 16 * u] = p;
            }
            #pragma unroll
            for (int o = 8; o; o >>= 1) rs += __shfl_xor_sync(0xffffffffu, rs, o);
            lrun[rr] = lrun[rr] * alpha + rs;
            ull al2 = dup2(alpha);
            mul2(accO2[rr][0], al2);
            mul2(accO2[rr][1], al2);
            mul2(accO2[rr][2], al2);
        }
        __syncthreads();

        // ---- GEMM2: O += P @ V (packed along output cols) ----
        #pragma unroll 4
        for (int j4 = 0; j4 < 16; j4++) {
            float4 p0 = *(float4*)&Ps[(y +  0) * 68 + j4 * 4];
            float4 p1 = *(float4*)&Ps[(y + 16) * 68 + j4 * 4];
            #pragma unroll
            for (int jj = 0; jj < 4; jj++) {
                const float* vb = &Vs[(j4 * 4 + jj) * 96 + x * 6];
                ull v0 = *(const ull*)(vb + 0);
                ull v1 = *(const ull*)(vb + 2);
                ull v2 = *(const ull*)(vb + 4);
                float pv0 = (jj == 0) ? p0.x : (jj == 1) ? p0.y : (jj == 2) ? p0.z : p0.w;
                float pv1 = (jj == 0) ? p1.x : (jj == 1) ? p1.y : (jj == 2) ? p1.z : p1.w;
                ull pd0 = dup2(pv0);
                ull pd1 = dup2(pv1);
                fma2(accO2[0][0], pd0, v0);
                fma2(accO2[0][1], pd0, v1);
                fma2(accO2[0][2], pd0, v2);
                fma2(accO2[1][0], pd1, v0);
                fma2(accO2[1][1], pd1, v1);
                fma2(accO2[1][2], pd1, v2);
            }
        }
    }

    // ---- epilogue: O/l + residual q, interleave heads into g_ctx ----
    int b = bh >> 2, nh = bh & 3;
    #pragma unroll
    for (int rr = 0; rr < 2; rr++) {
        int r = y + 16 * rr;
        int i = i0 + r;
        float inv = 1.f / lrun[rr];
        float* dst = &g_ctx[(((size_t)b * N_ + i) * NH_ + nh) * HD_ + x * 6];
        const float* qrow = &Qs[r * 96 + x * 6];
        #pragma unroll
        for (int tp = 0; tp < 3; tp++) {
            float lo, hi;
            unpack2(accO2[rr][tp], lo, hi);
            dst[2 * tp + 0] = lo * inv + qrow[2 * tp + 0];
            dst[2 * tp + 1] = hi * inv + qrow[2 * tp + 1];
        }
    }
}

// ---------------- K4: output projection + bias -----------------------------
__global__ void __launch_bounds__(256) k_proj(const float* __restrict__ proj_w,
                                              const float* __restrict__ proj_b,
                                              float* __restrict__ out) {
    int n0 = blockIdx.x * 64, m0 = blockIdx.y * 64;
    int xx = threadIdx.x & 15, yy = threadIdx.x >> 4;
    ull acc2[4][4] = {};
    gemm_nt64(g_ctx, proj_w, DIM_, m0, n0, xx, yy, acc2);
    #pragma unroll
    for (int rr = 0; rr < 4; rr++) {
        int m = m0 + yy + 16 * rr;
        #pragma unroll
        for (int u = 0; u < 4; u++) {
            int o = n0 + xx + 16 * u;
            out[(size_t)m * DIM_ + o] = hadd2(acc2[rr][u]) + proj_b[o];
        }
    }
}

// ---------------- launch ----------------------------------------------------
extern "C" void kernel_launch(void* const* d_in, const int* in_sizes, int n_in,
                              void* d_out, int out_size) {
    const float* x      = (const float*)d_in[0];
    const float* qkv_w  = (const float*)d_in[1];
    const float* proj_w = (const float*)d_in[2];
    const float* proj_b = (const float*)d_in[3];
    const float* pqw    = (const float*)d_in[4];
    const float* pkw    = (const float*)d_in[5];
    const float* pvw    = (const float*)d_in[6];
    const float* nqw    = (const float*)d_in[7];
    const float* nqb    = (const float*)d_in[8];
    const float* nkw    = (const float*)d_in[9];
    const float* nkb    = (const float*)d_in[10];
    const float* nvw    = (const float*)d_in[11];
    const float* nvb    = (const float*)d_in[12];
    const float* rph    = (const float*)d_in[13];
    const float* rpw    = (const float*)d_in[14];
    const float* rpt    = (const float*)d_in[15];
    float* out = (float*)d_out;

    cudaFuncSetAttribute(k_flash, cudaFuncAttributeMaxDynamicSharedMemorySize, 75776);

    k_qkv<<<dim3(18, 49), 256>>>(x, qkv_w);
    k_conv_ln<<<(BH_ * N_ * 3) / 4, 128>>>(pqw, pkw, pvw, nqw, nqb, nkw, nkb, nvw, nvb);
    k_flash<<<dim3(49, BH_), 256, 75776>>>(rph, rpw, rpt);
    k_proj<<<dim3(6, 49), 256>>>(proj_w, proj_b, out);
}

// round 5
// speedup vs baseline: 1.4211x; 1.0094x over previous
#include <cuda_runtime.h>
#include <cuda_bf16.h>
#include <math.h>

#define B_    2
#define NH_   4
#define T_    8
#define H_    14
#define W_    14
#define N_    1568
#define DIM_  384
#define HD_   96
#define BH_   (B_*NH_)
#define M_    (B_*N_)
#define EPS_  1e-6f
#define SCALE_ 0.1020620726159657f   // 96^-0.5

typedef unsigned long long ull;

// ---- packed f32x2 helpers (FFMA2: PTX-only) ------------------------------
__device__ __forceinline__ void fma2(ull& d, ull a, ull b) {
    asm("fma.rn.f32x2 %0, %1, %2, %0;" : "+l"(d) : "l"(a), "l"(b));
}
__device__ __forceinline__ float hadd2(ull v) {
    float lo, hi;
    asm("mov.b64 {%0, %1}, %2;" : "=f"(lo), "=f"(hi) : "l"(v));
    return lo + hi;
}
__device__ __forceinline__ ull dup2(float f) {
    ull d;
    asm("mov.b64 %0, {%1, %1};" : "=l"(d) : "f"(f));
    return d;
}
__device__ __forceinline__ void unpack2(ull v, float& lo, float& hi) {
    asm("mov.b64 {%0, %1}, %2;" : "=f"(lo), "=f"(hi) : "l"(v));
}

// ---------------- scratch ---------------------------------------------------
__device__ float g_q_raw[BH_ * N_ * HD_];
__device__ float g_k_raw[BH_ * N_ * HD_];
__device__ float g_v_raw[BH_ * N_ * HD_];
__device__ float g_q[BH_ * N_ * HD_];
__device__ float g_k[BH_ * N_ * HD_];
__device__ float g_v[BH_ * N_ * HD_];
__device__ float g_ctx[B_ * N_ * DIM_];

// ---------------- 64x64 NT GEMM core, packed-k FFMA2 -----------------------
__device__ __forceinline__ void gemm_nt64(const float* __restrict__ A,
                                          const float* __restrict__ Bw,
                                          int K, int m0, int n0,
                                          int xx, int yy, ull acc2[4][4]) {
    __shared__ float Xs[64 * 36];
    __shared__ float Ws[64 * 36];
    const int tid = yy * 16 + xx;
    for (int k0 = 0; k0 < K; k0 += 32) {
        __syncthreads();
        #pragma unroll
        for (int s = 0; s < 2; s++) {
            int idx = tid + 256 * s;
            int r = idx >> 3, c4 = idx & 7;
            *(float4*)&Xs[r * 36 + c4 * 4] =
                *(const float4*)&A[(size_t)(m0 + r) * K + k0 + c4 * 4];
            *(float4*)&Ws[r * 36 + c4 * 4] =
                *(const float4*)&Bw[(size_t)(n0 + r) * K + k0 + c4 * 4];
        }
        __syncthreads();
        #pragma unroll
        for (int c4 = 0; c4 < 8; c4++) {
            ulonglong2 a[4];
            #pragma unroll
            for (int rr = 0; rr < 4; rr++)
                a[rr] = *(ulonglong2*)&Xs[(yy + 16 * rr) * 36 + c4 * 4];
            #pragma unroll
            for (int u = 0; u < 4; u++) {
                ulonglong2 b = *(ulonglong2*)&Ws[(xx + 16 * u) * 36 + c4 * 4];
                #pragma unroll
                for (int rr = 0; rr < 4; rr++) {
                    fma2(acc2[rr][u], a[rr].x, b.x);
                    fma2(acc2[rr][u], a[rr].y, b.y);
                }
            }
        }
    }
}

// ---------------- K1: QKV projection ---------------------------------------
__global__ void __launch_bounds__(256) k_qkv(const float* __restrict__ x,
                                             const float* __restrict__ qkv_w) {
    int n0 = blockIdx.x * 64, m0 = blockIdx.y * 64;
    int xx = threadIdx.x & 15, yy = threadIdx.x >> 4;
    ull acc2[4][4] = {};
    gemm_nt64(x, qkv_w, DIM_, m0, n0, xx, yy, acc2);
    #pragma unroll
    for (int rr = 0; rr < 4; rr++) {
        int m = m0 + yy + 16 * rr;
        int b = m / N_, n = m - b * N_;
        #pragma unroll
        for (int u = 0; u < 4; u++) {
            int o = n0 + xx + 16 * u;
            int s = o / DIM_;
            int rem = o - s * DIM_;
            int head = rem / HD_;
            int c = rem - head * HD_;
            float* dst = (s == 0) ? g_q_raw : (s == 1) ? g_k_raw : g_v_raw;
            dst[((size_t)(b * NH_ + head) * N_ + n) * HD_ + c] = hadd2(acc2[rr][u]);
        }
    }
}

// ---------------- K2: conv3x3x3 + LayerNorm, warp per token ---------------
__global__ void __launch_bounds__(128) k_conv_ln(
        const float* __restrict__ wq, const float* __restrict__ wk,
        const float* __restrict__ wv,
        const float* __restrict__ gq, const float* __restrict__ bq,
        const float* __restrict__ gk, const float* __restrict__ bk,
        const float* __restrict__ gv, const float* __restrict__ bv) {
    int gid = blockIdx.x * 4 + (threadIdx.x >> 5);
    int lane = threadIdx.x & 31;
    int z = gid / (BH_ * N_);
    int rem0 = gid - z * (BH_ * N_);
    int bh = rem0 / N_;
    int n = rem0 - bh * N_;
    const float* inb  = (z == 0) ? g_q_raw : (z == 1) ? g_k_raw : g_v_raw;
    float*       outb = (z == 0) ? g_q     : (z == 1) ? g_k     : g_v;
    const float* wt    = (z == 0) ? wq : (z == 1) ? wk : wv;
    const float* gamma = (z == 0) ? gq : (z == 1) ? gk : gv;
    const float* beta  = (z == 0) ? bq : (z == 1) ? bk : bv;

    int tt = n / (H_ * W_);
    int rem = n - tt * (H_ * W_);
    int hh = rem / W_, ww = rem - (rem / W_) * W_;

    float val[3] = {0.f, 0.f, 0.f};
    #pragma unroll
    for (int dt = -1; dt <= 1; dt++) {
        int t2 = tt + dt;
        if (t2 < 0 || t2 >= T_) continue;
        #pragma unroll
        for (int dh = -1; dh <= 1; dh++) {
            int h2 = hh + dh;
            if (h2 < 0 || h2 >= H_) continue;
            #pragma unroll
            for (int dw = -1; dw <= 1; dw++) {
                int w2 = ww + dw;
                if (w2 < 0 || w2 >= W_) continue;
                int n2 = (t2 * H_ + h2) * W_ + w2;
                const float* src = &inb[((size_t)bh * N_ + n2) * HD_];
                int tap = (dt + 1) * 9 + (dh + 1) * 3 + (dw + 1);
                #pragma unroll
                for (int p = 0; p < 3; p++) {
                    int c = lane + 32 * p;
                    val[p] += wt[c * 27 + tap] * src[c];
                }
            }
        }
    }
    float s = val[0] + val[1] + val[2];
    float q = val[0]*val[0] + val[1]*val[1] + val[2]*val[2];
    #pragma unroll
    for (int o = 16; o; o >>= 1) {
        s += __shfl_xor_sync(0xffffffffu, s, o);
        q += __shfl_xor_sync(0xffffffffu, q, o);
    }
    float mean = s * (1.f / HD_);
    float var  = q * (1.f / HD_) - mean * mean;
    float rstd = rsqrtf(var + EPS_);
    float* dst = &outb[((size_t)bh * N_ + n) * HD_];
    #pragma unroll
    for (int p = 0; p < 3; p++) {
        int c = lane + 32 * p;
        dst[c] = (val[p] - mean) * rstd * gamma[c] + beta[c];
    }
}

// ---------------- K3: fused flash attention, 256 thr, FFMA2 ----------------
// No-max softmax: LN'd Q/K bound |s| <= ~20, exp sums stay in fp32 range.
// l-reduction deferred to the epilogue (one shfl tree instead of 25x2).
__global__ void __launch_bounds__(256, 3) k_flash(const float* __restrict__ rph,
                                                  const float* __restrict__ rpw,
                                                  const float* __restrict__ rpt) {
    extern __shared__ float sm[];
    float* Qs = sm;            // [32][96]
    float* Ks = sm + 3072;     // [64][100]  (pre-scaled by SCALE_)
    float* Vs = sm + 9472;     // [64][96]
    float* Ps = sm + 15616;    // [32][68]
    float* Rh = sm + 17792;    // [32][14]
    float* Rw = sm + 18240;    // [32][14]
    float* Rt = sm + 18688;    // [32][8]

    int bh = blockIdx.y;
    int i0 = blockIdx.x * 32;
    int tid = threadIdx.x;
    int x = tid & 15, y = tid >> 4;

    const float* Qg = g_q + ((size_t)bh * N_ + i0) * HD_;
    #pragma unroll
    for (int it = 0; it < 3; it++) {
        int idx = tid + 256 * it;            // 768 = 32 rows x 24 float4
        int r = idx / 24, c4 = idx % 24;
        *(float4*)&Qs[r * 96 + c4 * 4] = *(const float4*)&Qg[r * 96 + c4 * 4];
    }
    __syncthreads();

    // ---- rel-pos bias dots from Qs ----
    #pragma unroll
    for (int idx = tid; idx < 1152; idx += 256) {
        int r = idx / 36, e = idx - (idx / 36) * 36;
        int i = i0 + r;
        int it = i / 196;
        int rm = i - it * 196;
        int ih = rm / 14, iw = rm - ih * 14;
        const float* tab;
        float* dst;
        if (e < 14)      { tab = rph + (ih - e + 13) * HD_;        dst = &Rh[r * 14 + e]; }
        else if (e < 28) { int k = e - 14; tab = rpw + (iw - k + 13) * HD_; dst = &Rw[r * 14 + k]; }
        else             { int k = e - 28; tab = rpt + (it - k + 7) * HD_;  dst = &Rt[r * 8 + k]; }
        float s = 0.f;
        #pragma unroll 6
        for (int c4 = 0; c4 < 24; c4++) {
            float4 a = *(float4*)&Qs[r * 96 + c4 * 4];
            float4 b = *(const float4*)&tab[c4 * 4];
            s += a.x * b.x + a.y * b.y + a.z * b.z + a.w * b.w;
        }
        *dst = s;
    }

    float lpart[2] = {0.f, 0.f};             // per-thread partial softmax sums
    ull accO2[2][3] = {};

    const float* Kg = g_k + (size_t)bh * N_ * HD_;
    const float* Vg = g_v + (size_t)bh * N_ * HD_;

    for (int ch = 0; ch < 25; ch++) {
        int j0 = ch * 64;
        __syncthreads();
        #pragma unroll
        for (int it = 0; it < 6; it++) {
            int idx = tid + 256 * it;        // 1536 = 64 rows x 24 float4
            int row = idx / 24, c4 = idx % 24;
            int j = j0 + row;
            float4 kv, vv;
            if (j < N_) {
                kv = *(const float4*)&Kg[(size_t)j * 96 + c4 * 4];
                vv = *(const float4*)&Vg[(size_t)j * 96 + c4 * 4];
            } else {
                kv = make_float4(0.f, 0.f, 0.f, 0.f);
                vv = kv;
            }
            kv.x *= SCALE_; kv.y *= SCALE_; kv.z *= SCALE_; kv.w *= SCALE_;
            *(float4*)&Ks[row * 100 + c4 * 4] = kv;
            *(float4*)&Vs[row * 96  + c4 * 4] = vv;
        }
        __syncthreads();

        // ---- GEMM1: S = Q @ (K*scale)^T (packed along k) ----
        ull accS2[2][4] = {};
        #pragma unroll 6
        for (int c4 = 0; c4 < 24; c4++) {
            ulonglong2 a0 = *(ulonglong2*)&Qs[(y +  0) * 96 + c4 * 4];
            ulonglong2 a1 = *(ulonglong2*)&Qs[(y + 16) * 96 + c4 * 4];
            #pragma unroll
            for (int u = 0; u < 4; u++) {
                ulonglong2 b = *(ulonglong2*)&Ks[(x + 16 * u) * 100 + c4 * 4];
                fma2(accS2[0][u], a0.x, b.x);
                fma2(accS2[0][u], a0.y, b.y);
                fma2(accS2[1][u], a1.x, b.x);
                fma2(accS2[1][u], a1.y, b.y);
            }
        }

        // ---- bias + exp (no max subtraction; bounded scores) ----
        #pragma unroll
        for (int rr = 0; rr < 2; rr++) {
            int r = y + 16 * rr;
            #pragma unroll
            for (int u = 0; u < 4; u++) {
                int j = j0 + x + 16 * u;
                float p = 0.f;
                if (j < N_) {
                    int jt = j / 196;
                    int jr = j - jt * 196;
                    int jh = jr / 14;
                    int jw = jr - jh * 14;
                    float s = hadd2(accS2[rr][u])
                            + Rt[r * 8 + jt] + Rh[r * 14 + jh] + Rw[r * 14 + jw];
                    p = __expf(s);
                }
                lpart[rr] += p;
                Ps[r * 68 + x + 16 * u] = p;
            }
        }
        __syncthreads();

        // ---- GEMM2: O += P @ V (packed along output cols) ----
        #pragma unroll 4
        for (int j4 = 0; j4 < 16; j4++) {
            float4 p0 = *(float4*)&Ps[(y +  0) * 68 + j4 * 4];
            float4 p1 = *(float4*)&Ps[(y + 16) * 68 + j4 * 4];
            #pragma unroll
            for (int jj = 0; jj < 4; jj++) {
                const float* vb = &Vs[(j4 * 4 + jj) * 96 + x * 6];
                ull v0 = *(const ull*)(vb + 0);
                ull v1 = *(const ull*)(vb + 2);
                ull v2 = *(const ull*)(vb + 4);
                float pv0 = (jj == 0) ? p0.x : (jj == 1) ? p0.y : (jj == 2) ? p0.z : p0.w;
                float pv1 = (jj == 0) ? p1.x : (jj == 1) ? p1.y : (jj == 2) ? p1.z : p1.w;
                ull pd0 = dup2(pv0);
                ull pd1 = dup2(pv1);
                fma2(accO2[0][0], pd0, v0);
                fma2(accO2[0][1], pd0, v1);
                fma2(accO2[0][2], pd0, v2);
                fma2(accO2[1][0], pd1, v0);
                fma2(accO2[1][1], pd1, v1);
                fma2(accO2[1][2], pd1, v2);
            }
        }
    }

    // ---- epilogue: single l-reduction, O/l + residual q -> g_ctx ----
    #pragma unroll
    for (int rr = 0; rr < 2; rr++)
        #pragma unroll
        for (int o = 8; o; o >>= 1)
            lpart[rr] += __shfl_xor_sync(0xffffffffu, lpart[rr], o);

    int b = bh >> 2, nh = bh & 3;
    #pragma unroll
    for (int rr = 0; rr < 2; rr++) {
        int r = y + 16 * rr;
        int i = i0 + r;
        float inv = 1.f / lpart[rr];
        float* dst = &g_ctx[(((size_t)b * N_ + i) * NH_ + nh) * HD_ + x * 6];
        const float* qrow = &Qs[r * 96 + x * 6];
        #pragma unroll
        for (int tp = 0; tp < 3; tp++) {
            float lo, hi;
            unpack2(accO2[rr][tp], lo, hi);
            dst[2 * tp + 0] = lo * inv + qrow[2 * tp + 0];
            dst[2 * tp + 1] = hi * inv + qrow[2 * tp + 1];
        }
    }
}

// ---------------- K4: output projection + bias -----------------------------
__global__ void __launch_bounds__(256) k_proj(const float* __restrict__ proj_w,
                                              const float* __restrict__ proj_b,
                                              float* __restrict__ out) {
    int n0 = blockIdx.x * 64, m0 = blockIdx.y * 64;
    int xx = threadIdx.x & 15, yy = threadIdx.x >> 4;
    ull acc2[4][4] = {};
    gemm_nt64(g_ctx, proj_w, DIM_, m0, n0, xx, yy, acc2);
    #pragma unroll
    for (int rr = 0; rr < 4; rr++) {
        int m = m0 + yy + 16 * rr;
        #pragma unroll
        for (int u = 0; u < 4; u++) {
            int o = n0 + xx + 16 * u;
            out[(size_t)m * DIM_ + o] = hadd2(acc2[rr][u]) + proj_b[o];
        }
    }
}

// ---------------- launch ----------------------------------------------------
extern "C" void kernel_launch(void* const* d_in, const int* in_sizes, int n_in,
                              void* d_out, int out_size) {
    const float* x      = (const float*)d_in[0];
    const float* qkv_w  = (const float*)d_in[1];
    const float* proj_w = (const float*)d_in[2];
    const float* proj_b = (const float*)d_in[3];
    const float* pqw    = (const float*)d_in[4];
    const float* pkw    = (const float*)d_in[5];
    const float* pvw    = (const float*)d_in[6];
    const float* nqw    = (const float*)d_in[7];
    const float* nqb    = (const float*)d_in[8];
    const float* nkw    = (const float*)d_in[9];
    const float* nkb    = (const float*)d_in[10];
    const float* nvw    = (const float*)d_in[11];
    const float* nvb    = (const float*)d_in[12];
    const float* rph    = (const float*)d_in[13];
    const float* rpw    = (const float*)d_in[14];
    const float* rpt    = (const float*)d_in[15];
    float* out = (float*)d_out;

    cudaFuncSetAttribute(k_flash, cudaFuncAttributeMaxDynamicSharedMemorySize, 75776);

    k_qkv<<<dim3(18, 49), 256>>>(x, qkv_w);
    k_conv_ln<<<(BH_ * N_ * 3) / 4, 128>>>(pqw, pkw, pvw, nqw, nqb, nkw, nkb, nvw, nvb);
    k_flash<<<dim3(49, BH_), 256, 75776>>>(rph, rpw, rpt);
    k_proj<<<dim3(6, 49), 256>>>(proj_w, proj_b, out);
}

// round 6
// speedup vs baseline: 1.4647x; 1.0306x over previous
#include <cuda_runtime.h>
#include <cuda_bf16.h>
#include <math.h>

#define B_    2
#define NH_   4
#define T_    8
#define H_    14
#define W_    14
#define N_    1568
#define DIM_  384
#define HD_   96
#define BH_   (B_*NH_)
#define M_    (B_*N_)
#define EPS_  1e-6f
#define SCALE_ 0.1020620726159657f   // 96^-0.5

typedef unsigned long long ull;

// ---- packed f32x2 helpers (FFMA2: PTX-only) ------------------------------
__device__ __forceinline__ void fma2(ull& d, ull a, ull b) {
    asm("fma.rn.f32x2 %0, %1, %2, %0;" : "+l"(d) : "l"(a), "l"(b));
}
__device__ __forceinline__ float hadd2(ull v) {
    float lo, hi;
    asm("mov.b64 {%0, %1}, %2;" : "=f"(lo), "=f"(hi) : "l"(v));
    return lo + hi;
}
__device__ __forceinline__ ull dup2(float f) {
    ull d;
    asm("mov.b64 %0, {%1, %1};" : "=l"(d) : "f"(f));
    return d;
}
__device__ __forceinline__ void unpack2(ull v, float& lo, float& hi) {
    asm("mov.b64 {%0, %1}, %2;" : "=f"(lo), "=f"(hi) : "l"(v));
}

// ---------------- scratch ---------------------------------------------------
__device__ float g_q_raw[BH_ * N_ * HD_];
__device__ float g_k_raw[BH_ * N_ * HD_];
__device__ float g_v_raw[BH_ * N_ * HD_];
__device__ float g_q[BH_ * N_ * HD_];
__device__ float g_k[BH_ * N_ * HD_];
__device__ float g_v[BH_ * N_ * HD_];
__device__ float g_ctx[B_ * N_ * DIM_];

// ------- 64x64 NT GEMM core, packed-k FFMA2, double-buffered smem ----------
__device__ __forceinline__ void gemm_nt64(const float* __restrict__ A,
                                          const float* __restrict__ Bw,
                                          int K, int m0, int n0,
                                          int xx, int yy, ull acc2[4][4]) {
    __shared__ float Xs[2][64 * 36];
    __shared__ float Ws[2][64 * 36];
    const int tid = yy * 16 + xx;
    const int r0 = tid >> 3, c40 = tid & 7;
    const int r1 = (tid + 256) >> 3, c41 = tid & 7;

    // preload tile 0
    float4 pa0 = *(const float4*)&A[(size_t)(m0 + r0) * K + c40 * 4];
    float4 pb0 = *(const float4*)&Bw[(size_t)(n0 + r0) * K + c40 * 4];
    float4 pa1 = *(const float4*)&A[(size_t)(m0 + r1) * K + c41 * 4];
    float4 pb1 = *(const float4*)&Bw[(size_t)(n0 + r1) * K + c41 * 4];
    *(float4*)&Xs[0][r0 * 36 + c40 * 4] = pa0;
    *(float4*)&Ws[0][r0 * 36 + c40 * 4] = pb0;
    *(float4*)&Xs[0][r1 * 36 + c41 * 4] = pa1;
    *(float4*)&Ws[0][r1 * 36 + c41 * 4] = pb1;
    __syncthreads();

    int p = 0;
    for (int k0 = 0; k0 < K; k0 += 32) {
        // prefetch next tile into regs (overlaps with compute below)
        if (k0 + 32 < K) {
            pa0 = *(const float4*)&A[(size_t)(m0 + r0) * K + k0 + 32 + c40 * 4];
            pb0 = *(const float4*)&Bw[(size_t)(n0 + r0) * K + k0 + 32 + c40 * 4];
            pa1 = *(const float4*)&A[(size_t)(m0 + r1) * K + k0 + 32 + c41 * 4];
            pb1 = *(const float4*)&Bw[(size_t)(n0 + r1) * K + k0 + 32 + c41 * 4];
        }
        #pragma unroll
        for (int c4 = 0; c4 < 8; c4++) {
            ulonglong2 a[4];
            #pragma unroll
            for (int rr = 0; rr < 4; rr++)
                a[rr] = *(ulonglong2*)&Xs[p][(yy + 16 * rr) * 36 + c4 * 4];
            #pragma unroll
            for (int u = 0; u < 4; u++) {
                ulonglong2 b = *(ulonglong2*)&Ws[p][(xx + 16 * u) * 36 + c4 * 4];
                #pragma unroll
                for (int rr = 0; rr < 4; rr++) {
                    fma2(acc2[rr][u], a[rr].x, b.x);
                    fma2(acc2[rr][u], a[rr].y, b.y);
                }
            }
        }
        if (k0 + 32 < K) {
            *(float4*)&Xs[1 - p][r0 * 36 + c40 * 4] = pa0;
            *(float4*)&Ws[1 - p][r0 * 36 + c40 * 4] = pb0;
            *(float4*)&Xs[1 - p][r1 * 36 + c41 * 4] = pa1;
            *(float4*)&Ws[1 - p][r1 * 36 + c41 * 4] = pb1;
            __syncthreads();
            p ^= 1;
        }
    }
}

// ---------------- K1: QKV projection ---------------------------------------
__global__ void __launch_bounds__(256, 2) k_qkv(const float* __restrict__ x,
                                                const float* __restrict__ qkv_w) {
    int n0 = blockIdx.x * 64, m0 = blockIdx.y * 64;
    int xx = threadIdx.x & 15, yy = threadIdx.x >> 4;
    ull acc2[4][4] = {};
    gemm_nt64(x, qkv_w, DIM_, m0, n0, xx, yy, acc2);
    #pragma unroll
    for (int rr = 0; rr < 4; rr++) {
        int m = m0 + yy + 16 * rr;
        int b = m / N_, n = m - b * N_;
        #pragma unroll
        for (int u = 0; u < 4; u++) {
            int o = n0 + xx + 16 * u;
            int s = o / DIM_;
            int rem = o - s * DIM_;
            int head = rem / HD_;
            int c = rem - head * HD_;
            float* dst = (s == 0) ? g_q_raw : (s == 1) ? g_k_raw : g_v_raw;
            dst[((size_t)(b * NH_ + head) * N_ + n) * HD_ + c] = hadd2(acc2[rr][u]);
        }
    }
}

// ---------------- K2: conv3x3x3 + LayerNorm, warp per token ---------------
__global__ void __launch_bounds__(128) k_conv_ln(
        const float* __restrict__ wq, const float* __restrict__ wk,
        const float* __restrict__ wv,
        const float* __restrict__ gq, const float* __restrict__ bq,
        const float* __restrict__ gk, const float* __restrict__ bk,
        const float* __restrict__ gv, const float* __restrict__ bv) {
    int gid = blockIdx.x * 4 + (threadIdx.x >> 5);
    int lane = threadIdx.x & 31;
    int z = gid / (BH_ * N_);
    int rem0 = gid - z * (BH_ * N_);
    int bh = rem0 / N_;
    int n = rem0 - bh * N_;
    const float* inb  = (z == 0) ? g_q_raw : (z == 1) ? g_k_raw : g_v_raw;
    float*       outb = (z == 0) ? g_q     : (z == 1) ? g_k     : g_v;
    const float* wt    = (z == 0) ? wq : (z == 1) ? wk : wv;
    const float* gamma = (z == 0) ? gq : (z == 1) ? gk : gv;
    const float* beta  = (z == 0) ? bq : (z == 1) ? bk : bv;

    int tt = n / (H_ * W_);
    int rem = n - tt * (H_ * W_);
    int hh = rem / W_, ww = rem - (rem / W_) * W_;

    float val[3] = {0.f, 0.f, 0.f};
    #pragma unroll
    for (int dt = -1; dt <= 1; dt++) {
        int t2 = tt + dt;
        if (t2 < 0 || t2 >= T_) continue;
        #pragma unroll
        for (int dh = -1; dh <= 1; dh++) {
            int h2 = hh + dh;
            if (h2 < 0 || h2 >= H_) continue;
            #pragma unroll
            for (int dw = -1; dw <= 1; dw++) {
                int w2 = ww + dw;
                if (w2 < 0 || w2 >= W_) continue;
                int n2 = (t2 * H_ + h2) * W_ + w2;
                const float* src = &inb[((size_t)bh * N_ + n2) * HD_];
                int tap = (dt + 1) * 9 + (dh + 1) * 3 + (dw + 1);
                #pragma unroll
                for (int p = 0; p < 3; p++) {
                    int c = lane + 32 * p;
                    val[p] += wt[c * 27 + tap] * src[c];
                }
            }
        }
    }
    float s = val[0] + val[1] + val[2];
    float q = val[0]*val[0] + val[1]*val[1] + val[2]*val[2];
    #pragma unroll
    for (int o = 16; o; o >>= 1) {
        s += __shfl_xor_sync(0xffffffffu, s, o);
        q += __shfl_xor_sync(0xffffffffu, q, o);
    }
    float mean = s * (1.f / HD_);
    float var  = q * (1.f / HD_) - mean * mean;
    float rstd = rsqrtf(var + EPS_);
    float* dst = &outb[((size_t)bh * N_ + n) * HD_];
    #pragma unroll
    for (int p = 0; p < 3; p++) {
        int c = lane + 32 * p;
        dst[c] = (val[p] - mean) * rstd * gamma[c] + beta[c];
    }
}

// ---------------- K3: flash attention, 64-row tiles, R=4, FFMA2 ------------
// grid (25, 8). 64 Q rows/block, 64-key chunks. No-max softmax (bounded
// scores from LN'd q/k). 256 thr: rows y+16rr (rr<4), S cols x+16u.
__global__ void __launch_bounds__(256, 2) k_flash(const float* __restrict__ rph,
                                                  const float* __restrict__ rpw,
                                                  const float* __restrict__ rpt) {
    extern __shared__ float sm[];
    float* Qs = sm;            // [64][96]   24576B
    float* Ks = sm + 6144;     // [64][100]  (pre-scaled)
    float* Vs = sm + 12544;    // [64][96]
    float* Ps = sm + 18688;    // [64][68]
    float* Rh = sm + 23040;    // [64][14]
    float* Rw = sm + 23936;    // [64][14]
    float* Rt = sm + 24832;    // [64][8]    -> total 25344 floats = 101376B

    int bh = blockIdx.y;
    int i0 = blockIdx.x * 64;
    int tid = threadIdx.x;
    int x = tid & 15, y = tid >> 4;

    const float* Qg = g_q + ((size_t)bh * N_ + i0) * HD_;
    #pragma unroll
    for (int it = 0; it < 6; it++) {
        int idx = tid + 256 * it;            // 1536 = 64 rows x 24 float4
        int r = idx / 24, c4 = idx % 24;
        float4 qv = make_float4(0.f, 0.f, 0.f, 0.f);
        if (i0 + r < N_) qv = *(const float4*)&Qg[r * 96 + c4 * 4];
        *(float4*)&Qs[r * 96 + c4 * 4] = qv;
    }
    __syncthreads();

    // ---- rel-pos bias dots from Qs ----
    #pragma unroll
    for (int idx = tid; idx < 2304; idx += 256) {
        int r = idx / 36, e = idx - (idx / 36) * 36;
        int i = i0 + r;
        const float* tab = rph;   // dummy init
        float* dst;
        bool valid = (i < N_);
        int it = i / 196;
        int rm = i - it * 196;
        int ih = rm / 14, iw = rm - ih * 14;
        if (e < 14)      { tab = rph + (ih - e + 13) * HD_;        dst = &Rh[r * 14 + e]; }
        else if (e < 28) { int k = e - 14; tab = rpw + (iw - k + 13) * HD_; dst = &Rw[r * 14 + k]; }
        else             { int k = e - 28; tab = rpt + (it - k + 7) * HD_;  dst = &Rt[r * 8 + k]; }
        float s = 0.f;
        if (valid) {
            #pragma unroll 6
            for (int c4 = 0; c4 < 24; c4++) {
                float4 a = *(float4*)&Qs[r * 96 + c4 * 4];
                float4 b = *(const float4*)&tab[c4 * 4];
                s += a.x * b.x + a.y * b.y + a.z * b.z + a.w * b.w;
            }
        }
        *dst = s;
    }

    float lpart[4] = {0.f, 0.f, 0.f, 0.f};
    ull accO2[4][3] = {};

    const float* Kg = g_k + (size_t)bh * N_ * HD_;
    const float* Vg = g_v + (size_t)bh * N_ * HD_;

    for (int ch = 0; ch < 25; ch++) {
        int j0 = ch * 64;
        __syncthreads();
        #pragma unroll
        for (int it = 0; it < 6; it++) {
            int idx = tid + 256 * it;        // 1536 = 64 rows x 24 float4
            int row = idx / 24, c4 = idx % 24;
            int j = j0 + row;
            float4 kv, vv;
            if (j < N_) {
                kv = *(const float4*)&Kg[(size_t)j * 96 + c4 * 4];
                vv = *(const float4*)&Vg[(size_t)j * 96 + c4 * 4];
            } else {
                kv = make_float4(0.f, 0.f, 0.f, 0.f);
                vv = kv;
            }
            kv.x *= SCALE_; kv.y *= SCALE_; kv.z *= SCALE_; kv.w *= SCALE_;
            *(float4*)&Ks[row * 100 + c4 * 4] = kv;
            *(float4*)&Vs[row * 96  + c4 * 4] = vv;
        }
        __syncthreads();

        // ---- GEMM1: S = Q @ (K*scale)^T (packed along k) ----
        ull accS2[4][4] = {};
        #pragma unroll 6
        for (int c4 = 0; c4 < 24; c4++) {
            ulonglong2 a[4];
            #pragma unroll
            for (int rr = 0; rr < 4; rr++)
                a[rr] = *(ulonglong2*)&Qs[(y + 16 * rr) * 96 + c4 * 4];
            #pragma unroll
            for (int u = 0; u < 4; u++) {
                ulonglong2 b = *(ulonglong2*)&Ks[(x + 16 * u) * 100 + c4 * 4];
                #pragma unroll
                for (int rr = 0; rr < 4; rr++) {
                    fma2(accS2[rr][u], a[rr].x, b.x);
                    fma2(accS2[rr][u], a[rr].y, b.y);
                }
            }
        }

        // ---- bias + exp (no max subtraction; bounded scores) ----
        #pragma unroll
        for (int rr = 0; rr < 4; rr++) {
            int r = y + 16 * rr;
            #pragma unroll
            for (int u = 0; u < 4; u++) {
                int j = j0 + x + 16 * u;
                float p = 0.f;
                if (j < N_) {
                    int jt = j / 196;
                    int jr = j - jt * 196;
                    int jh = jr / 14;
                    int jw = jr - jh * 14;
                    float s = hadd2(accS2[rr][u])
                            + Rt[r * 8 + jt] + Rh[r * 14 + jh] + Rw[r * 14 + jw];
                    p = __expf(s);
                }
                lpart[rr] += p;
                Ps[r * 68 + x + 16 * u] = p;
            }
        }
        __syncthreads();

        // ---- GEMM2: O += P @ V (packed along output cols) ----
        #pragma unroll 4
        for (int j4 = 0; j4 < 16; j4++) {
            float4 p[4];
            #pragma unroll
            for (int rr = 0; rr < 4; rr++)
                p[rr] = *(float4*)&Ps[(y + 16 * rr) * 68 + j4 * 4];
            #pragma unroll
            for (int jj = 0; jj < 4; jj++) {
                const float* vb = &Vs[(j4 * 4 + jj) * 96 + x * 6];
                ull v0 = *(const ull*)(vb + 0);
                ull v1 = *(const ull*)(vb + 2);
                ull v2 = *(const ull*)(vb + 4);
                #pragma unroll
                for (int rr = 0; rr < 4; rr++) {
                    float pv = (jj == 0) ? p[rr].x : (jj == 1) ? p[rr].y
                             : (jj == 2) ? p[rr].z : p[rr].w;
                    ull pd = dup2(pv);
                    fma2(accO2[rr][0], pd, v0);
                    fma2(accO2[rr][1], pd, v1);
                    fma2(accO2[rr][2], pd, v2);
                }
            }
        }
    }

    // ---- epilogue: single l-reduction, O/l + residual q -> g_ctx ----
    #pragma unroll
    for (int rr = 0; rr < 4; rr++)
        #pragma unroll
        for (int o = 8; o; o >>= 1)
            lpart[rr] += __shfl_xor_sync(0xffffffffu, lpart[rr], o);

    int b = bh >> 2, nh = bh & 3;
    #pragma unroll
    for (int rr = 0; rr < 4; rr++) {
        int r = y + 16 * rr;
        int i = i0 + r;
        if (i >= N_) continue;
        float inv = 1.f / lpart[rr];
        float* dst = &g_ctx[(((size_t)b * N_ + i) * NH_ + nh) * HD_ + x * 6];
        const float* qrow = &Qs[r * 96 + x * 6];
        #pragma unroll
        for (int tp = 0; tp < 3; tp++) {
            float lo, hi;
            unpack2(accO2[rr][tp], lo, hi);
            dst[2 * tp + 0] = lo * inv + qrow[2 * tp + 0];
            dst[2 * tp + 1] = hi * inv + qrow[2 * tp + 1];
        }
    }
}

// ---------------- K4: output projection + bias -----------------------------
__global__ void __launch_bounds__(256, 2) k_proj(const float* __restrict__ proj_w,
                                                 const float* __restrict__ proj_b,
                                                 float* __restrict__ out) {
    int n0 = blockIdx.x * 64, m0 = blockIdx.y * 64;
    int xx = threadIdx.x & 15, yy = threadIdx.x >> 4;
    ull acc2[4][4] = {};
    gemm_nt64(g_ctx, proj_w, DIM_, m0, n0, xx, yy, acc2);
    #pragma unroll
    for (int rr = 0; rr < 4; rr++) {
        int m = m0 + yy + 16 * rr;
        #pragma unroll
        for (int u = 0; u < 4; u++) {
            int o = n0 + xx + 16 * u;
            out[(size_t)m * DIM_ + o] = hadd2(acc2[rr][u]) + proj_b[o];
        }
    }
}

// ---------------- launch ----------------------------------------------------
extern "C" void kernel_launch(void* const* d_in, const int* in_sizes, int n_in,
                              void* d_out, int out_size) {
    const float* x      = (const float*)d_in[0];
    const float* qkv_w  = (const float*)d_in[1];
    const float* proj_w = (const float*)d_in[2];
    const float* proj_b = (const float*)d_in[3];
    const float* pqw    = (const float*)d_in[4];
    const float* pkw    = (const float*)d_in[5];
    const float* pvw    = (const float*)d_in[6];
    const float* nqw    = (const float*)d_in[7];
    const float* nqb    = (const float*)d_in[8];
    const float* nkw    = (const float*)d_in[9];
    const float* nkb    = (const float*)d_in[10];
    const float* nvw    = (const float*)d_in[11];
    const float* nvb    = (const float*)d_in[12];
    const float* rph    = (const float*)d_in[13];
    const float* rpw    = (const float*)d_in[14];
    const float* rpt    = (const float*)d_in[15];
    float* out = (float*)d_out;

    cudaFuncSetAttribute(k_flash, cudaFuncAttributeMaxDynamicSharedMemorySize, 101376);

    k_qkv<<<dim3(18, 49), 256>>>(x, qkv_w);
    k_conv_ln<<<(BH_ * N_ * 3) / 4, 128>>>(pqw, pkw, pvw, nqw, nqb, nkw, nkb, nvw, nvb);
    k_flash<<<dim3(25, BH_), 256, 101376>>>(rph, rpw, rpt);
    k_proj<<<dim3(6, 49), 256>>>(proj_w, proj_b, out);
}